// round 9
// baseline (speedup 1.0000x reference)
#include <cuda_runtime.h>
#include <cuda_fp16.h>
#include <cstdint>

typedef unsigned long long u64;
typedef unsigned int u32;

#define NTOK  49
#define ROWP  130
#define WSTR  6370            // 49*130 per-window Q/K/V stride (floats)
#define SSTR  9604            // per-window S: 4 heads * 49*49

// ---- smem float offsets ----
#define KK_F  0               // K [2][49][130]
#define VV_F  12740           // V
#define QQ_F  25480           // Q  (dead after P2a; O staging [2][49][128] overlays)
#define SCR_F 38220           // scratch: P1/P3 fp16 tiles  UNION  S [2][4][2401]
// scratch internals (floats):
#define AH_F  38220           // A hi tile: 64 rows x 128 fp16 (swizzled) = 4096 fl
#define AL_F  42316
#define BH_F  46412           // B hi tile: 64 n-rows x 128 fp16 = 4096 fl
#define BL_F  50508
#define SS_F  38220           // S region (19208 fl) after P1
#define SMEM_FLOATS 57432
#define SMEM_BYTES  (SMEM_FLOATS * 4)

__device__ __forceinline__ u64 ffma2(u64 a, u64 b, u64 c) {
    u64 d; asm("fma.rn.f32x2 %0, %1, %2, %3;" : "=l"(d) : "l"(a), "l"(b), "l"(c)); return d;
}
__device__ __forceinline__ u64 dup2(float x) {
    u64 d; u32 u = __float_as_uint(x);
    asm("mov.b64 %0, {%1, %1};" : "=l"(d) : "r"(u)); return d;
}
__device__ __forceinline__ void unpack2(u64 v, float& x, float& y) {
    u32 ux, uy; asm("mov.b64 {%0, %1}, %2;" : "=r"(ux), "=r"(uy) : "l"(v));
    x = __uint_as_float(ux); y = __uint_as_float(uy);
}
__device__ __forceinline__ int imin(int a, int b) { return a < b ? a : b; }

__device__ __forceinline__ void ldsm_x4(u32& r0, u32& r1, u32& r2, u32& r3, u32 addr) {
    asm volatile("ldmatrix.sync.aligned.m8n8.x4.shared.b16 {%0,%1,%2,%3}, [%4];"
                 : "=r"(r0), "=r"(r1), "=r"(r2), "=r"(r3) : "r"(addr));
}
__device__ __forceinline__ void ldsm_x2(u32& r0, u32& r1, u32 addr) {
    asm volatile("ldmatrix.sync.aligned.m8n8.x2.shared.b16 {%0,%1}, [%2];"
                 : "=r"(r0), "=r"(r1) : "r"(addr));
}
__device__ __forceinline__ void mma16816(float* c, const u32* a, const u32* b) {
    asm volatile(
        "mma.sync.aligned.m16n8k16.row.col.f32.f16.f16.f32 "
        "{%0,%1,%2,%3}, {%4,%5,%6,%7}, {%8,%9}, {%0,%1,%2,%3};"
        : "+f"(c[0]), "+f"(c[1]), "+f"(c[2]), "+f"(c[3])
        : "r"(a[0]), "r"(a[1]), "r"(a[2]), "r"(a[3]), "r"(b[0]), "r"(b[1]));
}

// split f -> (hi fp16, lo fp16); pack two k-adjacent elements into u32 (low half = even k)
__device__ __forceinline__ void split_pair(float f0, float f1, u32& hi, u32& lo) {
    __half h0 = __float2half_rn(f0), h1 = __float2half_rn(f1);
    float  r0 = f0 - __half2float(h0), r1 = f1 - __half2float(h1);
    __half l0 = __float2half_rn(r0), l1 = __float2half_rn(r1);
    hi = ((u32)__half_as_ushort(h1) << 16) | __half_as_ushort(h0);
    lo = ((u32)__half_as_ushort(l1) << 16) | __half_as_ushort(l0);
}
// swizzled byte offset inside a 64-row x 128-fp16 tile (256 B rows, XOR on 16B units)
__device__ __forceinline__ u32 tile_off(u32 r, u32 unit) {
    return r * 256 + ((unit ^ (r & 7)) * 16);
}

__global__ __launch_bounds__(512, 1)
void win_attn_kernel(const float* __restrict__ x,
                     const float* __restrict__ qkv_w,
                     const float* __restrict__ qkv_b,
                     const float* __restrict__ proj_w,
                     const float* __restrict__ proj_b,
                     const float* __restrict__ bias_table,
                     const float* __restrict__ mask,
                     const int*   __restrict__ rel_index,
                     float*       __restrict__ out)
{
    extern __shared__ float sm[];
    const int tid = threadIdx.x;
    const int wid = tid >> 5, ln = tid & 31;
    const int b2  = blockIdx.x * 2;
    const float scale = 0.17677669529663687f;

    u32 sb;
    asm("{ .reg .u64 t; cvta.to.shared.u64 t, %1; cvt.u32.u64 %0, t; }" : "=r"(sb) : "l"(sm));
    const u32 AHb = sb + AH_F * 4, ALb = sb + AL_F * 4;
    const u32 BHb = sb + BH_F * 4, BLb = sb + BL_F * 4;

    const int m   = wid & 3;          // warp's M-tile (16 rows)
    const int nt0 = wid >> 2;         // warp's first N-tile within 8

    // ===================== P1: qkv GEMM per window =====================
    for (int win = 0; win < 2; win++) {
        // convert x -> A hi/lo fp16 tiles (64 rows x 128 k, swizzled)
        const float* xw = x + (size_t)(b2 + win) * NTOK * 128;
        for (int i = tid; i < 64 * 64; i += 512) {
            int r = i >> 6, kp = i & 63;
            float f0 = 0.f, f1 = 0.f;
            if (r < NTOK) { f0 = __ldg(xw + r * 128 + 2 * kp); f1 = __ldg(xw + r * 128 + 2 * kp + 1); }
            u32 hi, lo; split_pair(f0, f1, hi, lo);
            u32 off = tile_off(r, kp >> 2) + (kp & 3) * 4;
            *(u32*)((char*)sm + AH_F * 4 + off) = hi;
            *(u32*)((char*)sm + AL_F * 4 + off) = lo;
        }
        __syncthreads();

        for (int c = 0; c < 6; c++) {
            // convert qkv_w chunk -> B hi/lo ([n][k] rows, swizzled)
            for (int i = tid; i < 64 * 64; i += 512) {
                int nr = i >> 6, kp = i & 63;
                int g = c * 64 + nr;
                float f0 = __ldg(qkv_w + (size_t)(2 * kp)     * 384 + g);
                float f1 = __ldg(qkv_w + (size_t)(2 * kp + 1) * 384 + g);
                u32 hi, lo; split_pair(f0, f1, hi, lo);
                u32 off = tile_off(nr, kp >> 2) + (kp & 3) * 4;
                *(u32*)((char*)sm + BH_F * 4 + off) = hi;
                *(u32*)((char*)sm + BL_F * 4 + off) = lo;
            }
            __syncthreads();

            float acc[2][4];
            #pragma unroll
            for (int q = 0; q < 2; q++)
                #pragma unroll
                for (int j = 0; j < 4; j++) acc[q][j] = 0.f;

            #pragma unroll
            for (int kc = 0; kc < 8; kc++) {
                u32 ah[4], al[4];
                {
                    u32 r = m * 16 + (ln & 15);
                    u32 off = tile_off(r, kc * 2 + (ln >> 4));
                    ldsm_x4(ah[0], ah[1], ah[2], ah[3], AHb + off);
                    ldsm_x4(al[0], al[1], al[2], al[3], ALb + off);
                }
                #pragma unroll
                for (int q = 0; q < 2; q++) {
                    int nt = nt0 + q * 4;
                    u32 r = nt * 8 + (ln & 7);
                    u32 off = tile_off(r, kc * 2 + ((ln >> 3) & 1));
                    u32 bh[2], bl[2];
                    ldsm_x2(bh[0], bh[1], BHb + off);
                    ldsm_x2(bl[0], bl[1], BLb + off);
                    mma16816(acc[q], ah, bh);
                    mma16816(acc[q], al, bh);
                    mma16816(acc[q], ah, bl);
                }
            }

            // store C -> Q/K/V fp32 smem (+bias, Q*scale)
            #pragma unroll
            for (int q = 0; q < 2; q++) {
                int nt = nt0 + q * 4;
                int g  = c * 64 + nt * 8 + 2 * (ln & 3);
                int tc = g >> 7, cc = g & 127;
                float bv0 = __ldg(qkv_b + g), bv1 = __ldg(qkv_b + g + 1);
                float mult = (tc == 0) ? scale : 1.f;
                float* reg = sm + (tc == 0 ? QQ_F : tc == 1 ? KK_F : VV_F) + win * WSTR;
                int r0 = m * 16 + (ln >> 2);
                if (r0 < NTOK) {
                    float2* d = (float2*)(reg + r0 * ROWP + cc);
                    *d = make_float2((acc[q][0] + bv0) * mult, (acc[q][1] + bv1) * mult);
                }
                int r1 = r0 + 8;
                if (r1 < NTOK) {
                    float2* d = (float2*)(reg + r1 * ROWP + cc);
                    *d = make_float2((acc[q][2] + bv0) * mult, (acc[q][3] + bv1) * mult);
                }
            }
            __syncthreads();
        }
    }

    // ===================== P2a: S = QK^T + bias + mask =====================
    float* S4 = sm + SS_F;
    for (int tile = tid; tile < 1352; tile += 512) {
        int win = tile >= 676;
        int r = tile - win * 676;
        int h = r / 169; int rr = r - h * 169;
        int nb = rr / 13, mb = rr - nb * 13;
        const float* Qw = sm + QQ_F + win * WSTR + h * 32;
        const float* Kw = sm + KK_F + win * WSTR + h * 32;
        const float* qp[4]; const float* kp[4];
        #pragma unroll
        for (int i = 0; i < 4; i++) {
            qp[i] = Qw + imin(nb * 4 + i, 48) * ROWP;
            kp[i] = Kw + imin(mb * 4 + i, 48) * ROWP;
        }
        u64 acc[4][4];
        #pragma unroll
        for (int i = 0; i < 4; i++)
            #pragma unroll
            for (int j = 0; j < 4; j++) acc[i][j] = 0ull;
        #pragma unroll 4
        for (int jp = 0; jp < 16; jp++) {
            u64 qv[4], kv[4];
            #pragma unroll
            for (int i = 0; i < 4; i++) qv[i] = *(const u64*)(qp[i] + 2 * jp);
            #pragma unroll
            for (int j = 0; j < 4; j++) kv[j] = *(const u64*)(kp[j] + 2 * jp);
            #pragma unroll
            for (int i = 0; i < 4; i++)
                #pragma unroll
                for (int j = 0; j < 4; j++) acc[i][j] = ffma2(qv[i], kv[j], acc[i][j]);
        }
        const float* maskw = mask + (size_t)((b2 + win) & 63) * NTOK * NTOK;
        float* Sh = S4 + win * SSTR + h * 2401;
        #pragma unroll
        for (int i = 0; i < 4; i++) {
            int n = nb * 4 + i;
            #pragma unroll
            for (int j = 0; j < 4; j++) {
                int mm = mb * 4 + j;
                if (n < NTOK && mm < NTOK) {
                    float a0, a1; unpack2(acc[i][j], a0, a1);
                    int idx = n * NTOK + mm;
                    Sh[n * NTOK + mm] = a0 + a1
                        + __ldg(bias_table + rel_index[idx] * 4 + h) + __ldg(maskw + idx);
                }
            }
        }
    }
    __syncthreads();

    // ===================== P2b: softmax =====================
    for (int row = wid; row < 392; row += 16) {
        int win = row >= 196; int rem = row - win * 196;
        int h = rem / NTOK, n = rem - h * NTOK;
        float* Sr = S4 + win * SSTR + h * 2401 + n * NTOK;
        float v0 = Sr[ln];
        float v1 = (ln + 32 < NTOK) ? Sr[ln + 32] : -1e30f;
        float mx = fmaxf(v0, v1);
        #pragma unroll
        for (int o = 16; o; o >>= 1) mx = fmaxf(mx, __shfl_xor_sync(0xffffffffu, mx, o));
        float e0 = __expf(v0 - mx);
        float e1 = (ln + 32 < NTOK) ? __expf(v1 - mx) : 0.f;
        float s = e0 + e1;
        #pragma unroll
        for (int o = 16; o; o >>= 1) s += __shfl_xor_sync(0xffffffffu, s, o);
        float inv = 1.f / s;
        Sr[ln] = e0 * inv;
        if (ln + 32 < NTOK) Sr[ln + 32] = e1 * inv;
    }
    __syncthreads();

    // ===================== P2c: O = S @ V  -> Ost [2][49][128] over Q ========
    float* Ost = sm + QQ_F;
    if (tid < 416) {
        int win = tid >= 208;
        int idx = tid - win * 208;
        int nb = idx >> 4, chb = idx & 15;
        int h = chb >> 2;
        const float* vb = sm + VV_F + win * WSTR + chb * 8;
        const float* Srow[4];
        #pragma unroll
        for (int i = 0; i < 4; i++)
            Srow[i] = S4 + win * SSTR + h * 2401 + imin(nb * 4 + i, 48) * NTOK;
        u64 acc[4][4];
        #pragma unroll
        for (int i = 0; i < 4; i++)
            #pragma unroll
            for (int j = 0; j < 4; j++) acc[i][j] = 0ull;
        #pragma unroll 2
        for (int mm = 0; mm < NTOK; mm++) {
            u64 vv[4];
            #pragma unroll
            for (int j = 0; j < 4; j++) vv[j] = *(const u64*)(vb + mm * ROWP + 2 * j);
            #pragma unroll
            for (int i = 0; i < 4; i++) {
                u64 sd = dup2(Srow[i][mm]);
                #pragma unroll
                for (int j = 0; j < 4; j++) acc[i][j] = ffma2(sd, vv[j], acc[i][j]);
            }
        }
        #pragma unroll
        for (int i = 0; i < 4; i++) {
            int n = nb * 4 + i;
            if (n < NTOK) {
                #pragma unroll
                for (int j = 0; j < 4; j++) {
                    int ch = chb * 8 + 2 * j;
                    float a0, a1; unpack2(acc[i][j], a0, a1);
                    Ost[(win * NTOK + n) * 128 + ch]     = a0;
                    Ost[(win * NTOK + n) * 128 + ch + 1] = a1;
                }
            }
        }
    }
    __syncthreads();

    // ===================== P3: out = O @ proj_w + proj_b =====================
    for (int win = 0; win < 2; win++) {
        // convert O -> A hi/lo tiles
        const float* ow = Ost + win * NTOK * 128;
        for (int i = tid; i < 64 * 64; i += 512) {
            int r = i >> 6, kp = i & 63;
            float f0 = 0.f, f1 = 0.f;
            if (r < NTOK) { f0 = ow[r * 128 + 2 * kp]; f1 = ow[r * 128 + 2 * kp + 1]; }
            u32 hi, lo; split_pair(f0, f1, hi, lo);
            u32 off = tile_off(r, kp >> 2) + (kp & 3) * 4;
            *(u32*)((char*)sm + AH_F * 4 + off) = hi;
            *(u32*)((char*)sm + AL_F * 4 + off) = lo;
        }
        __syncthreads();

        for (int c = 0; c < 2; c++) {
            for (int i = tid; i < 64 * 64; i += 512) {
                int nr = i >> 6, kp = i & 63;
                int g = c * 64 + nr;
                float f0 = __ldg(proj_w + (size_t)(2 * kp)     * 128 + g);
                float f1 = __ldg(proj_w + (size_t)(2 * kp + 1) * 128 + g);
                u32 hi, lo; split_pair(f0, f1, hi, lo);
                u32 off = tile_off(nr, kp >> 2) + (kp & 3) * 4;
                *(u32*)((char*)sm + BH_F * 4 + off) = hi;
                *(u32*)((char*)sm + BL_F * 4 + off) = lo;
            }
            __syncthreads();

            float acc[2][4];
            #pragma unroll
            for (int q = 0; q < 2; q++)
                #pragma unroll
                for (int j = 0; j < 4; j++) acc[q][j] = 0.f;

            #pragma unroll
            for (int kc = 0; kc < 8; kc++) {
                u32 ah[4], al[4];
                {
                    u32 r = m * 16 + (ln & 15);
                    u32 off = tile_off(r, kc * 2 + (ln >> 4));
                    ldsm_x4(ah[0], ah[1], ah[2], ah[3], AHb + off);
                    ldsm_x4(al[0], al[1], al[2], al[3], ALb + off);
                }
                #pragma unroll
                for (int q = 0; q < 2; q++) {
                    int nt = nt0 + q * 4;
                    u32 r = nt * 8 + (ln & 7);
                    u32 off = tile_off(r, kc * 2 + ((ln >> 3) & 1));
                    u32 bh[2], bl[2];
                    ldsm_x2(bh[0], bh[1], BHb + off);
                    ldsm_x2(bl[0], bl[1], BLb + off);
                    mma16816(acc[q], ah, bh);
                    mma16816(acc[q], al, bh);
                    mma16816(acc[q], ah, bl);
                }
            }

            float* og = out + (size_t)(b2 + win) * NTOK * 128;
            #pragma unroll
            for (int q = 0; q < 2; q++) {
                int nt = nt0 + q * 4;
                int g  = c * 64 + nt * 8 + 2 * (ln & 3);
                float b0 = __ldg(proj_b + g), b1 = __ldg(proj_b + g + 1);
                int r0 = m * 16 + (ln >> 2);
                if (r0 < NTOK)
                    *(float2*)(og + r0 * 128 + g) = make_float2(acc[q][0] + b0, acc[q][1] + b1);
                int r1 = r0 + 8;
                if (r1 < NTOK)
                    *(float2*)(og + r1 * 128 + g) = make_float2(acc[q][2] + b0, acc[q][3] + b1);
            }
            __syncthreads();
        }
    }
}

extern "C" void kernel_launch(void* const* d_in, const int* in_sizes, int n_in,
                              void* d_out, int out_size)
{
    const float* x = nullptr; const float* qkv_w = nullptr; const float* qkv_b = nullptr;
    const float* proj_w = nullptr; const float* proj_b = nullptr;
    const float* bias_table = nullptr; const float* mask = nullptr;
    const int* rel_index = nullptr;

    for (int i = 0; i < n_in; i++) {
        switch (in_sizes[i]) {
            case 25690112: x          = (const float*)d_in[i]; break;
            case 49152:    qkv_w      = (const float*)d_in[i]; break;
            case 384:      qkv_b      = (const float*)d_in[i]; break;
            case 16384:    proj_w     = (const float*)d_in[i]; break;
            case 128:      proj_b     = (const float*)d_in[i]; break;
            case 676:      bias_table = (const float*)d_in[i]; break;
            case 153664:   mask       = (const float*)d_in[i]; break;
            case 2401:     rel_index  = (const int*)  d_in[i]; break;
            default: break;
        }
    }

    float* out = (float*)d_out;

    cudaFuncSetAttribute(win_attn_kernel,
                         cudaFuncAttributeMaxDynamicSharedMemorySize, SMEM_BYTES);

    win_attn_kernel<<<2048, 512, SMEM_BYTES>>>(
        x, qkv_w, qkv_b, proj_w, proj_b, bias_table, mask, rel_index, out);
}

// round 10
// speedup vs baseline: 2.1340x; 2.1340x over previous
#include <cuda_runtime.h>
#include <cuda_fp16.h>
#include <cstdint>

typedef unsigned long long u64;
typedef unsigned int u32;

#define NROW  200704              // 4096*49
#define NFLAT 25690112            // NROW*128
#define NTOK  49

// ---------------- global scratch ----------------
__device__ __half g_xh[NFLAT];
__device__ __half g_xl[NFLAT];
__device__ float  g_q[NFLAT];
__device__ float  g_k[NFLAT];
__device__ float  g_v[NFLAT];
__device__ __half g_oh[NFLAT];
__device__ __half g_ol[NFLAT];
__device__ __half g_wqh[49152];   // qkv_w, n-major [384][128]
__device__ __half g_wql[49152];
__device__ __half g_wph[16384];   // proj_w, n-major [128][128]
__device__ __half g_wpl[16384];

// ---------------- helpers ----------------
__device__ __forceinline__ void fsplit(float f, __half& h, __half& l) {
    h = __float2half_rn(f);
    l = __float2half_rn(f - __half2float(h));
}
__device__ __forceinline__ u64 ffma2(u64 a, u64 b, u64 c) {
    u64 d; asm("fma.rn.f32x2 %0, %1, %2, %3;" : "=l"(d) : "l"(a), "l"(b), "l"(c)); return d;
}
__device__ __forceinline__ u64 dup2(float x) {
    u64 d; u32 u = __float_as_uint(x);
    asm("mov.b64 %0, {%1, %1};" : "=l"(d) : "r"(u)); return d;
}
__device__ __forceinline__ void unpack2(u64 v, float& x, float& y) {
    u32 ux, uy; asm("mov.b64 {%0, %1}, %2;" : "=r"(ux), "=r"(uy) : "l"(v));
    x = __uint_as_float(ux); y = __uint_as_float(uy);
}
__device__ __forceinline__ int imin(int a, int b) { return a < b ? a : b; }

__device__ __forceinline__ void ldsm_x4(u32* r, u32 addr) {
    asm volatile("ldmatrix.sync.aligned.m8n8.x4.shared.b16 {%0,%1,%2,%3}, [%4];"
                 : "=r"(r[0]), "=r"(r[1]), "=r"(r[2]), "=r"(r[3]) : "r"(addr));
}
__device__ __forceinline__ void mma16816(float* c, const u32* a, const u32* b) {
    asm volatile(
        "mma.sync.aligned.m16n8k16.row.col.f32.f16.f16.f32 "
        "{%0,%1,%2,%3}, {%4,%5,%6,%7}, {%8,%9}, {%0,%1,%2,%3};"
        : "+f"(c[0]), "+f"(c[1]), "+f"(c[2]), "+f"(c[3])
        : "r"(a[0]), "r"(a[1]), "r"(a[2]), "r"(a[3]), "r"(b[0]), "r"(b[1]));
}
// byte offset inside a [rows][128-fp16] tile, 256 B/row, XOR swizzle on 16B units
__device__ __forceinline__ u32 toff(u32 r, u32 unit) {
    return r * 256 + ((unit ^ (r & 7)) * 16);
}

// ================= K0a: x -> fp16 hi/lo =================
__global__ void cvt_x(const float* __restrict__ x) {
    int i = blockIdx.x * blockDim.x + threadIdx.x;
    int st = gridDim.x * blockDim.x;
    for (; i < NFLAT / 4; i += st) {
        float4 f = __ldg((const float4*)x + i);
        __half h0, l0, h1, l1, h2, l2, h3, l3;
        fsplit(f.x, h0, l0); fsplit(f.y, h1, l1);
        fsplit(f.z, h2, l2); fsplit(f.w, h3, l3);
        ((__half2*)g_xh)[2 * i]     = __halves2half2(h0, h1);
        ((__half2*)g_xh)[2 * i + 1] = __halves2half2(h2, h3);
        ((__half2*)g_xl)[2 * i]     = __halves2half2(l0, l1);
        ((__half2*)g_xl)[2 * i + 1] = __halves2half2(l2, l3);
    }
}

// ================= K0b: weights -> fp16 hi/lo, n-major =================
__global__ void cvt_w(const float* __restrict__ qkv_w, const float* __restrict__ proj_w) {
    int t = blockIdx.x * blockDim.x + threadIdx.x;
    int st = gridDim.x * blockDim.x;
    for (int i = t; i < 49152; i += st) {
        int n = i >> 7, k = i & 127;
        __half h, l; fsplit(__ldg(qkv_w + k * 384 + n), h, l);
        g_wqh[i] = h; g_wql[i] = l;
    }
    for (int i = t; i < 16384; i += st) {
        int n = i >> 7, k = i & 127;
        __half h, l; fsplit(__ldg(proj_w + k * 128 + n), h, l);
        g_wph[i] = h; g_wpl[i] = l;
    }
}

// ================= generic 128x64x128 3-term fp16 GEMM body =================
// A tiles (hi/lo) 128x128 fp16 swizzled @ sh half-offsets 0 / 16384
// B tiles (hi/lo)  64x128 fp16 swizzled @ 32768 / 40960
#define SA_H 0
#define SA_L 16384
#define SB_H 32768
#define SB_L 40960
#define GEMM_SMEM (49152 * 2)   // 96 KB

template<bool QKV>
__device__ __forceinline__ void gemm_body(const __half* Ah, const __half* Al,
                                          const __half* Bh, const __half* Bl,
                                          const float* __restrict__ bias,
                                          float* dst0, int c)
{
    extern __shared__ __half sh[];
    const int tid = threadIdx.x;
    const int wid = tid >> 5, ln = tid & 31;
    const int m0 = blockIdx.y * 128;

    // copy A (128 rows x 16 uint4)
    {
        const uint4* sh4 = (const uint4*)Ah + (size_t)m0 * 16;
        const uint4* sl4 = (const uint4*)Al + (size_t)m0 * 16;
        for (int i = tid; i < 2048; i += 256) {
            int r = i >> 4, u = i & 15;
            u32 off = toff(r, u);
            *(uint4*)((char*)sh + SA_H * 2 + off) = __ldg(sh4 + i);
            *(uint4*)((char*)sh + SA_L * 2 + off) = __ldg(sl4 + i);
        }
    }
    // copy B chunk (64 rows x 16 uint4)
    {
        const uint4* bh4 = (const uint4*)Bh + (size_t)c * 1024;
        const uint4* bl4 = (const uint4*)Bl + (size_t)c * 1024;
        for (int i = tid; i < 1024; i += 256) {
            int r = i >> 4, u = i & 15;
            u32 off = toff(r, u);
            *(uint4*)((char*)sh + SB_H * 2 + off) = __ldg(bh4 + i);
            *(uint4*)((char*)sh + SB_L * 2 + off) = __ldg(bl4 + i);
        }
    }
    __syncthreads();

    u32 sb;
    asm("{ .reg .u64 t; cvta.to.shared.u64 t, %1; cvt.u32.u64 %0, t; }" : "=r"(sb) : "l"(sh));
    const u32 aH = sb + SA_H * 2, aL = sb + SA_L * 2;
    const u32 bH = sb + SB_H * 2, bL = sb + SB_L * 2;

    const int mw = wid & 3;       // M warp tile (32 rows)
    const int nw = wid >> 2;      // N warp tile (32 cols)

    float acc[2][4][4];
    #pragma unroll
    for (int i = 0; i < 2; i++)
        #pragma unroll
        for (int j = 0; j < 4; j++)
            #pragma unroll
            for (int q = 0; q < 4; q++) acc[i][j][q] = 0.f;

    #pragma unroll
    for (int kc = 0; kc < 8; kc++) {
        u32 ah[2][4], al[2][4];
        #pragma unroll
        for (int mi = 0; mi < 2; mi++) {
            u32 off = toff(mw * 32 + mi * 16 + (ln & 15), kc * 2 + (ln >> 4));
            ldsm_x4(ah[mi], aH + off);
            ldsm_x4(al[mi], aL + off);
        }
        u32 bh[4][2], bl[4][2];
        #pragma unroll
        for (int p = 0; p < 2; p++) {
            int g = ln >> 3;
            u32 off = toff(nw * 32 + p * 16 + (g >> 1) * 8 + (ln & 7), kc * 2 + (g & 1));
            u32 t4[4], t4l[4];
            ldsm_x4(t4, bH + off);
            ldsm_x4(t4l, bL + off);
            bh[2 * p][0] = t4[0];  bh[2 * p][1] = t4[1];
            bh[2 * p + 1][0] = t4[2]; bh[2 * p + 1][1] = t4[3];
            bl[2 * p][0] = t4l[0]; bl[2 * p][1] = t4l[1];
            bl[2 * p + 1][0] = t4l[2]; bl[2 * p + 1][1] = t4l[3];
        }
        #pragma unroll
        for (int mi = 0; mi < 2; mi++)
            #pragma unroll
            for (int nj = 0; nj < 4; nj++) {
                mma16816(acc[mi][nj], ah[mi], bh[nj]);
                mma16816(acc[mi][nj], al[mi], bh[nj]);
                mma16816(acc[mi][nj], ah[mi], bl[nj]);
            }
    }

    // epilogue
    const float scale = 0.17677669529663687f;
    #pragma unroll
    for (int mi = 0; mi < 2; mi++)
        #pragma unroll
        for (int nj = 0; nj < 4; nj++) {
            int cl = nw * 32 + nj * 8 + 2 * (ln & 3);
            int gcol = c * 64 + cl;
            float b0 = __ldg(bias + gcol), b1 = __ldg(bias + gcol + 1);
            float mult = 1.f;
            float* dst; int col;
            if (QKV) {
                dst = (c < 2) ? g_q : (c < 4) ? g_k : g_v;
                col = (c & 1) * 64 + cl;
                if (c < 2) mult = scale;
            } else {
                dst = dst0;
                col = gcol;
            }
            int r = m0 + mw * 32 + mi * 16 + (ln >> 2);
            *(float2*)(dst + (size_t)r * 128 + col) =
                make_float2((acc[mi][nj][0] + b0) * mult, (acc[mi][nj][1] + b1) * mult);
            *(float2*)(dst + (size_t)(r + 8) * 128 + col) =
                make_float2((acc[mi][nj][2] + b0) * mult, (acc[mi][nj][3] + b1) * mult);
        }
}

__global__ __launch_bounds__(256, 2)
void gemm_qkv(const float* __restrict__ qkv_b) {
    gemm_body<true>(g_xh, g_xl, g_wqh, g_wql, qkv_b, nullptr, blockIdx.x);
}
__global__ __launch_bounds__(256, 2)
void gemm_proj(const float* __restrict__ proj_b, float* __restrict__ out) {
    gemm_body<false>(g_oh, g_ol, g_wph, g_wpl, proj_b, out, blockIdx.x);
}

// ================= K2: per-window attention =================
#define RP 132
#define QF 0
#define KF (NTOK * RP)
#define VF (2 * NTOK * RP)
#define SF (3 * NTOK * RP)            // + 2*2401 floats
#define ATTN_SMEM ((SF + 2 * 2401) * 4)

__global__ __launch_bounds__(256, 2)
void attn_kernel(const float* __restrict__ bias_table,
                 const float* __restrict__ mask,
                 const int*   __restrict__ rel_index)
{
    extern __shared__ float sm[];
    const int tid = threadIdx.x;
    const int wid = tid >> 5, ln = tid & 31;
    const int win = blockIdx.x;
    const size_t rbase = (size_t)win * NTOK * 128;

    // load Q/K/V (already scaled/biased)
    {
        const float4* qs = (const float4*)(g_q + rbase);
        const float4* ks = (const float4*)(g_k + rbase);
        const float4* vs = (const float4*)(g_v + rbase);
        for (int i = tid; i < NTOK * 32; i += 256) {
            int r = i >> 5, cq = i & 31;
            *(float4*)(sm + QF + r * RP + cq * 4) = __ldg(qs + i);
            *(float4*)(sm + KF + r * RP + cq * 4) = __ldg(ks + i);
            *(float4*)(sm + VF + r * RP + cq * 4) = __ldg(vs + i);
        }
    }
    __syncthreads();

    const float* maskw = mask + (size_t)(win & 63) * NTOK * NTOK;

    for (int hp = 0; hp < 2; hp++) {
        // ---- S = QK^T + bias + mask for heads 2hp, 2hp+1 ----
        for (int it = tid; it < 338; it += 256) {
            int hs = it / 169, rr = it - hs * 169;
            int h = hp * 2 + hs;
            int nb = rr / 13, mb = rr - nb * 13;
            const float* qp[4]; const float* kp[4];
            #pragma unroll
            for (int i = 0; i < 4; i++) {
                qp[i] = sm + QF + imin(nb * 4 + i, 48) * RP + h * 32;
                kp[i] = sm + KF + imin(mb * 4 + i, 48) * RP + h * 32;
            }
            u64 acc[4][4];
            #pragma unroll
            for (int i = 0; i < 4; i++)
                #pragma unroll
                for (int j = 0; j < 4; j++) acc[i][j] = 0ull;
            #pragma unroll 4
            for (int jp = 0; jp < 16; jp++) {
                u64 qv[4], kv[4];
                #pragma unroll
                for (int i = 0; i < 4; i++) qv[i] = *(const u64*)(qp[i] + 2 * jp);
                #pragma unroll
                for (int j = 0; j < 4; j++) kv[j] = *(const u64*)(kp[j] + 2 * jp);
                #pragma unroll
                for (int i = 0; i < 4; i++)
                    #pragma unroll
                    for (int j = 0; j < 4; j++) acc[i][j] = ffma2(qv[i], kv[j], acc[i][j]);
            }
            float* Sh = sm + SF + hs * 2401;
            #pragma unroll
            for (int i = 0; i < 4; i++) {
                int n = nb * 4 + i;
                #pragma unroll
                for (int j = 0; j < 4; j++) {
                    int m = mb * 4 + j;
                    if (n < NTOK && m < NTOK) {
                        float a0, a1; unpack2(acc[i][j], a0, a1);
                        int idx = n * NTOK + m;
                        Sh[n * NTOK + m] = a0 + a1
                            + __ldg(bias_table + rel_index[idx] * 4 + h) + __ldg(maskw + idx);
                    }
                }
            }
        }
        __syncthreads();

        // ---- softmax (98 rows) ----
        for (int row = wid; row < 98; row += 8) {
            int hs = row >= NTOK; int n = row - hs * NTOK;
            float* Sr = sm + SF + hs * 2401 + n * NTOK;
            float v0 = Sr[ln];
            float v1 = (ln + 32 < NTOK) ? Sr[ln + 32] : -1e30f;
            float mx = fmaxf(v0, v1);
            #pragma unroll
            for (int o = 16; o; o >>= 1) mx = fmaxf(mx, __shfl_xor_sync(0xffffffffu, mx, o));
            float e0 = __expf(v0 - mx);
            float e1 = (ln + 32 < NTOK) ? __expf(v1 - mx) : 0.f;
            float s = e0 + e1;
            #pragma unroll
            for (int o = 16; o; o >>= 1) s += __shfl_xor_sync(0xffffffffu, s, o);
            float inv = 1.f / s;
            Sr[ln] = e0 * inv;
            if (ln + 32 < NTOK) Sr[ln + 32] = e1 * inv;
        }
        __syncthreads();

        // ---- O = S @ V, write fp16 hi/lo ----
        if (tid < 208) {
            int nb = tid >> 4;                // 0..12
            int cb = tid & 15;
            int hs = cb >> 3;                 // head within pair
            int h  = hp * 2 + hs;
            int chl = (cb & 7) * 4;           // 4 channels
            const float* vb = sm + VF + h * 32 + chl;
            const float* Srow[4];
            #pragma unroll
            for (int i = 0; i < 4; i++)
                Srow[i] = sm + SF + hs * 2401 + imin(nb * 4 + i, 48) * NTOK;
            u64 acc[4][2];
            #pragma unroll
            for (int i = 0; i < 4; i++) { acc[i][0] = 0ull; acc[i][1] = 0ull; }
            #pragma unroll 2
            for (int m = 0; m < NTOK; m++) {
                u64 v0 = *(const u64*)(vb + m * RP);
                u64 v1 = *(const u64*)(vb + m * RP + 2);
                #pragma unroll
                for (int i = 0; i < 4; i++) {
                    u64 sd = dup2(Srow[i][m]);
                    acc[i][0] = ffma2(sd, v0, acc[i][0]);
                    acc[i][1] = ffma2(sd, v1, acc[i][1]);
                }
            }
            #pragma unroll
            for (int i = 0; i < 4; i++) {
                int n = nb * 4 + i;
                if (n < NTOK) {
                    size_t grow = rbase + (size_t)n * 128 + h * 32 + chl;
                    #pragma unroll
                    for (int jj = 0; jj < 2; jj++) {
                        float o0, o1; unpack2(acc[i][jj], o0, o1);
                        __half h0, l0, h1, l1;
                        fsplit(o0, h0, l0); fsplit(o1, h1, l1);
                        *((__half2*)(g_oh + grow + 2 * jj)) = __halves2half2(h0, h1);
                        *((__half2*)(g_ol + grow + 2 * jj)) = __halves2half2(l0, l1);
                    }
                }
            }
        }
        __syncthreads();
    }
}

// ================= launch =================
extern "C" void kernel_launch(void* const* d_in, const int* in_sizes, int n_in,
                              void* d_out, int out_size)
{
    const float* x = nullptr; const float* qkv_w = nullptr; const float* qkv_b = nullptr;
    const float* proj_w = nullptr; const float* proj_b = nullptr;
    const float* bias_table = nullptr; const float* mask = nullptr;
    const int* rel_index = nullptr;

    for (int i = 0; i < n_in; i++) {
        switch (in_sizes[i]) {
            case 25690112: x          = (const float*)d_in[i]; break;
            case 49152:    qkv_w      = (const float*)d_in[i]; break;
            case 384:      qkv_b      = (const float*)d_in[i]; break;
            case 16384:    proj_w     = (const float*)d_in[i]; break;
            case 128:      proj_b     = (const float*)d_in[i]; break;
            case 676:      bias_table = (const float*)d_in[i]; break;
            case 153664:   mask       = (const float*)d_in[i]; break;
            case 2401:     rel_index  = (const int*)  d_in[i]; break;
            default: break;
        }
    }
    float* out = (float*)d_out;

    static bool attr_done = false;
    if (!attr_done) {
        cudaFuncSetAttribute(gemm_qkv,  cudaFuncAttributeMaxDynamicSharedMemorySize, GEMM_SMEM);
        cudaFuncSetAttribute(gemm_proj, cudaFuncAttributeMaxDynamicSharedMemorySize, GEMM_SMEM);
        cudaFuncSetAttribute(attn_kernel, cudaFuncAttributeMaxDynamicSharedMemorySize, ATTN_SMEM);
        attr_done = true;
    }

    cvt_x<<<2048, 256>>>(x);
    cvt_w<<<64, 256>>>(qkv_w, proj_w);
    gemm_qkv<<<dim3(6, 1568), 256, GEMM_SMEM>>>(qkv_b);
    attn_kernel<<<4096, 256, ATTN_SMEM>>>(bias_table, mask, rel_index);
    gemm_proj<<<dim3(2, 1568), 256, GEMM_SMEM>>>(proj_b, out);
}

// round 12
// speedup vs baseline: 2.6478x; 1.2408x over previous
#include <cuda_runtime.h>
#include <cuda_fp16.h>
#include <cstdint>

typedef unsigned long long u64;
typedef unsigned int u32;

#define NROW  200704              // 4096*49
#define NFLAT 25690112            // NROW*128
#define NTOK  49

// ---------------- global scratch ----------------
__device__ float  g_q[NFLAT];
__device__ float  g_k[NFLAT];
__device__ float  g_v[NFLAT];
__device__ __half g_oh[NFLAT];
__device__ __half g_ol[NFLAT];
__device__ __half g_wqh[49152];   // qkv_w, n-major [384][128]
__device__ __half g_wql[49152];
__device__ __half g_wph[16384];   // proj_w, n-major [128][128]
__device__ __half g_wpl[16384];

// ---------------- helpers ----------------
__device__ __forceinline__ void fsplit(float f, __half& h, __half& l) {
    h = __float2half_rn(f);
    l = __float2half_rn(f - __half2float(h));
}
__device__ __forceinline__ u64 ffma2(u64 a, u64 b, u64 c) {
    u64 d; asm("fma.rn.f32x2 %0, %1, %2, %3;" : "=l"(d) : "l"(a), "l"(b), "l"(c)); return d;
}
__device__ __forceinline__ u64 dup2(float x) {
    u64 d; u32 u = __float_as_uint(x);
    asm("mov.b64 %0, {%1, %1};" : "=l"(d) : "r"(u)); return d;
}
__device__ __forceinline__ void unpack2(u64 v, float& x, float& y) {
    u32 ux, uy; asm("mov.b64 {%0, %1}, %2;" : "=r"(ux), "=r"(uy) : "l"(v));
    x = __uint_as_float(ux); y = __uint_as_float(uy);
}
__device__ __forceinline__ int imin(int a, int b) { return a < b ? a : b; }

__device__ __forceinline__ void ldsm_x4(u32* r, u32 addr) {
    asm volatile("ldmatrix.sync.aligned.m8n8.x4.shared.b16 {%0,%1,%2,%3}, [%4];"
                 : "=r"(r[0]), "=r"(r[1]), "=r"(r[2]), "=r"(r[3]) : "r"(addr));
}
__device__ __forceinline__ void ldsm_x2(u32* r, u32 addr) {
    asm volatile("ldmatrix.sync.aligned.m8n8.x2.shared.b16 {%0,%1}, [%2];"
                 : "=r"(r[0]), "=r"(r[1]) : "r"(addr));
}
__device__ __forceinline__ void mma16816(float* c, const u32* a, const u32* b) {
    asm volatile(
        "mma.sync.aligned.m16n8k16.row.col.f32.f16.f16.f32 "
        "{%0,%1,%2,%3}, {%4,%5,%6,%7}, {%8,%9}, {%0,%1,%2,%3};"
        : "+f"(c[0]), "+f"(c[1]), "+f"(c[2]), "+f"(c[3])
        : "r"(a[0]), "r"(a[1]), "r"(a[2]), "r"(a[3]), "r"(b[0]), "r"(b[1]));
}
// byte offset in a [rows][128-fp16] tile: 256 B/row, XOR swizzle on 16B units
__device__ __forceinline__ u32 toff(u32 r, u32 unit) {
    return r * 256 + ((unit ^ (r & 7)) * 16);
}

// ================= K0: weights -> fp16 hi/lo, n-major =================
__global__ void cvt_w(const float* __restrict__ qkv_w, const float* __restrict__ proj_w) {
    int t = blockIdx.x * blockDim.x + threadIdx.x;
    int st = gridDim.x * blockDim.x;
    for (int i = t; i < 49152; i += st) {
        int n = i >> 7, k = i & 127;
        __half h, l; fsplit(__ldg(qkv_w + k * 384 + n), h, l);
        g_wqh[i] = h; g_wql[i] = l;
    }
    for (int i = t; i < 16384; i += st) {
        int n = i >> 7, k = i & 127;
        __half h, l; fsplit(__ldg(proj_w + k * 128 + n), h, l);
        g_wph[i] = h; g_wpl[i] = l;
    }
}

// ================= GEMM (A-resident, N-chunk loop inside) =================
#define SA_H 0
#define SA_L 16384
#define SB_H 32768
#define SB_L 40960
#define GEMM_SMEM (49152 * 2)   // 96 KB

template<bool QKV>
__device__ __forceinline__ void gemm_run(const float* __restrict__ xA,
                                         const __half* Ah16, const __half* Al16,
                                         const __half* Bh, const __half* Bl,
                                         const float* __restrict__ bias,
                                         float* dst0, int nchunks)
{
    extern __shared__ __half sh[];
    const int tid = threadIdx.x;
    const int wid = tid >> 5, ln = tid & 31;
    const int m0 = blockIdx.x * 128;

    // ---- load A (128 rows x 128 k) ----
    if (QKV) {
        for (int i = tid; i < 2048; i += 256) {
            int r = i >> 4, u = i & 15;
            const float* src = xA + (size_t)(m0 + r) * 128 + u * 8;
            float4 fa = __ldg((const float4*)src);
            float4 fb = __ldg((const float4*)(src + 4));
            __half h[8], l[8];
            fsplit(fa.x, h[0], l[0]); fsplit(fa.y, h[1], l[1]);
            fsplit(fa.z, h[2], l[2]); fsplit(fa.w, h[3], l[3]);
            fsplit(fb.x, h[4], l[4]); fsplit(fb.y, h[5], l[5]);
            fsplit(fb.z, h[6], l[6]); fsplit(fb.w, h[7], l[7]);
            u32 off = toff(r, u);
            *(uint4*)((char*)sh + SA_H * 2 + off) = *(uint4*)h;
            *(uint4*)((char*)sh + SA_L * 2 + off) = *(uint4*)l;
        }
    } else {
        const uint4* ah4 = (const uint4*)Ah16 + (size_t)m0 * 16;
        const uint4* al4 = (const uint4*)Al16 + (size_t)m0 * 16;
        for (int i = tid; i < 2048; i += 256) {
            int r = i >> 4, u = i & 15;
            u32 off = toff(r, u);
            *(uint4*)((char*)sh + SA_H * 2 + off) = __ldg(ah4 + i);
            *(uint4*)((char*)sh + SA_L * 2 + off) = __ldg(al4 + i);
        }
    }

    u32 sb;
    asm("{ .reg .u64 t; cvta.to.shared.u64 t, %1; cvt.u32.u64 %0, t; }" : "=r"(sb) : "l"(sh));
    const u32 aH = sb + SA_H * 2, aL = sb + SA_L * 2;
    const u32 bH = sb + SB_H * 2, bL = sb + SB_L * 2;
    const int mw = wid & 3, nw = wid >> 2;
    const float scale = 0.17677669529663687f;

    for (int c = 0; c < nchunks; c++) {
        {
            const uint4* bh4 = (const uint4*)Bh + (size_t)c * 1024;
            const uint4* bl4 = (const uint4*)Bl + (size_t)c * 1024;
            for (int i = tid; i < 1024; i += 256) {
                int r = i >> 4, u = i & 15;
                u32 off = toff(r, u);
                *(uint4*)((char*)sh + SB_H * 2 + off) = __ldg(bh4 + i);
                *(uint4*)((char*)sh + SB_L * 2 + off) = __ldg(bl4 + i);
            }
        }
        __syncthreads();

        float acc[2][4][4];
        #pragma unroll
        for (int i = 0; i < 2; i++)
            #pragma unroll
            for (int j = 0; j < 4; j++)
                #pragma unroll
                for (int q = 0; q < 4; q++) acc[i][j][q] = 0.f;

        #pragma unroll
        for (int kc = 0; kc < 8; kc++) {
            u32 ah[2][4], al[2][4];
            #pragma unroll
            for (int mi = 0; mi < 2; mi++) {
                u32 off = toff(mw * 32 + mi * 16 + (ln & 15), kc * 2 + (ln >> 4));
                ldsm_x4(ah[mi], aH + off);
                ldsm_x4(al[mi], aL + off);
            }
            u32 bhf[4][2], blf[4][2];
            #pragma unroll
            for (int p = 0; p < 2; p++) {
                int g = ln >> 3;
                u32 off = toff(nw * 32 + p * 16 + (g >> 1) * 8 + (ln & 7), kc * 2 + (g & 1));
                u32 t4[4], t4l[4];
                ldsm_x4(t4, bH + off);
                ldsm_x4(t4l, bL + off);
                bhf[2 * p][0] = t4[0];  bhf[2 * p][1] = t4[1];
                bhf[2 * p + 1][0] = t4[2]; bhf[2 * p + 1][1] = t4[3];
                blf[2 * p][0] = t4l[0]; blf[2 * p][1] = t4l[1];
                blf[2 * p + 1][0] = t4l[2]; blf[2 * p + 1][1] = t4l[3];
            }
            #pragma unroll
            for (int mi = 0; mi < 2; mi++)
                #pragma unroll
                for (int nj = 0; nj < 4; nj++) {
                    mma16816(acc[mi][nj], ah[mi], bhf[nj]);
                    mma16816(acc[mi][nj], al[mi], bhf[nj]);
                    mma16816(acc[mi][nj], ah[mi], blf[nj]);
                }
        }

        #pragma unroll
        for (int mi = 0; mi < 2; mi++)
            #pragma unroll
            for (int nj = 0; nj < 4; nj++) {
                int cl = nw * 32 + nj * 8 + 2 * (ln & 3);
                int gcol = c * 64 + cl;
                float b0 = __ldg(bias + gcol), b1 = __ldg(bias + gcol + 1);
                float mult = 1.f;
                float* dst; int col;
                if (QKV) {
                    dst = (c < 2) ? g_q : (c < 4) ? g_k : g_v;
                    col = (c & 1) * 64 + cl;
                    if (c < 2) mult = scale;
                } else {
                    dst = dst0;
                    col = gcol;
                }
                int r = m0 + mw * 32 + mi * 16 + (ln >> 2);
                *(float2*)(dst + (size_t)r * 128 + col) =
                    make_float2((acc[mi][nj][0] + b0) * mult, (acc[mi][nj][1] + b1) * mult);
                *(float2*)(dst + (size_t)(r + 8) * 128 + col) =
                    make_float2((acc[mi][nj][2] + b0) * mult, (acc[mi][nj][3] + b1) * mult);
            }
        __syncthreads();
    }
}

__global__ __launch_bounds__(256, 2)
void gemm_qkv(const float* __restrict__ x, const float* __restrict__ qkv_b) {
    gemm_run<true>(x, nullptr, nullptr, g_wqh, g_wql, qkv_b, nullptr, 6);
}
__global__ __launch_bounds__(256, 2)
void gemm_proj(const float* __restrict__ proj_b, float* __restrict__ out) {
    gemm_run<false>(nullptr, g_oh, g_ol, g_wph, g_wpl, proj_b, out, 2);
}

// ================= attention =================
// smem (bytes): fp16 tiles QH@0 QL@16384 KH@32768 KL@49152 (each 64x128 fp16, swizzled)
// floats: S @ 16384 fl (2 heads x 49 x 56), V @ VPF (49 x 128)
#define SPF 16384
#define SROW 56                  // FIX: >= 7 N-tiles * 8 = 56 (was 52 -> cross-row store clobber)
#define SHS (NTOK * SROW)        // 2744
#define VPF (SPF + 2 * SHS)      // 21872
#define ATTN_SMEM ((VPF + NTOK * 128) * 4)   // 112,576 B

__global__ __launch_bounds__(256, 2)
void attn_kernel(const float* __restrict__ bias_table,
                 const float* __restrict__ mask,
                 const int*   __restrict__ rel_index)
{
    extern __shared__ float sm[];
    char* smc = (char*)sm;
    const int tid = threadIdx.x;
    const int wid = tid >> 5, ln = tid & 31;
    const int win = blockIdx.x;
    const size_t rbase = (size_t)win * NTOK * 128;

    u32 sb;
    asm("{ .reg .u64 t; cvta.to.shared.u64 t, %1; cvt.u32.u64 %0, t; }" : "=r"(sb) : "l"(sm));
    const u32 QHb = sb, QLb = sb + 16384, KHb = sb + 32768, KLb = sb + 49152;

    // ---- load Q/K -> fp16 hi/lo swizzled tiles (rows 49..63 zero); V -> fp32 ----
    for (int i = tid; i < 1024; i += 256) {
        int r = i >> 4, u = i & 15;
        uint4 qh, ql, kh, kl;
        if (r < NTOK) {
            const float* qs = g_q + rbase + (size_t)r * 128 + u * 8;
            const float* ks = g_k + rbase + (size_t)r * 128 + u * 8;
            float4 a = __ldg((const float4*)qs), b = __ldg((const float4*)(qs + 4));
            float4 c = __ldg((const float4*)ks), d = __ldg((const float4*)(ks + 4));
            __half h[8], l[8];
            fsplit(a.x, h[0], l[0]); fsplit(a.y, h[1], l[1]);
            fsplit(a.z, h[2], l[2]); fsplit(a.w, h[3], l[3]);
            fsplit(b.x, h[4], l[4]); fsplit(b.y, h[5], l[5]);
            fsplit(b.z, h[6], l[6]); fsplit(b.w, h[7], l[7]);
            qh = *(uint4*)h; ql = *(uint4*)l;
            fsplit(c.x, h[0], l[0]); fsplit(c.y, h[1], l[1]);
            fsplit(c.z, h[2], l[2]); fsplit(c.w, h[3], l[3]);
            fsplit(d.x, h[4], l[4]); fsplit(d.y, h[5], l[5]);
            fsplit(d.z, h[6], l[6]); fsplit(d.w, h[7], l[7]);
            kh = *(uint4*)h; kl = *(uint4*)l;
        } else {
            qh = ql = kh = kl = make_uint4(0, 0, 0, 0);
        }
        u32 off = toff(r, u);
        *(uint4*)(smc + off)         = qh;
        *(uint4*)(smc + 16384 + off) = ql;
        *(uint4*)(smc + 32768 + off) = kh;
        *(uint4*)(smc + 49152 + off) = kl;
    }
    for (int i = tid; i < NTOK * 32; i += 256) {
        int r = i >> 5, cq = i & 31;
        *(float4*)(sm + VPF + r * 128 + cq * 4) =
            __ldg((const float4*)(g_v + rbase + (size_t)r * 128) + cq);
    }
    __syncthreads();

    const float* maskw = mask + (size_t)(win & 63) * NTOK * NTOK;

    for (int hp = 0; hp < 2; hp++) {
        // ---- QK^T via HMMA (2 heads x 4 Mt x 7 Nt = 56 warp jobs) ----
        for (int job = wid; job < 56; job += 8) {
            int hs = job / 28; int r2 = job - hs * 28;
            int Mt = r2 / 7, Nt = r2 - Mt * 7;
            int h = hp * 2 + hs;
            float acc[4] = {0.f, 0.f, 0.f, 0.f};
            #pragma unroll
            for (int kc = 0; kc < 2; kc++) {
                u32 ah[4], al[4];
                u32 aoff = toff(Mt * 16 + (ln & 15), h * 4 + kc * 2 + (ln >> 4));
                ldsm_x4(ah, QHb + aoff);
                ldsm_x4(al, QLb + aoff);
                u32 bh[2], bl[2];
                u32 boff = toff(Nt * 8 + (ln & 7), h * 4 + kc * 2 + ((ln >> 3) & 1));
                ldsm_x2(bh, KHb + boff);
                ldsm_x2(bl, KLb + boff);
                mma16816(acc, ah, bh);
                mma16816(acc, al, bh);
                mma16816(acc, ah, bl);
            }
            float* Sh = sm + SPF + hs * SHS;
            int r0 = Mt * 16 + (ln >> 2);
            int col = Nt * 8 + 2 * (ln & 3);
            if (r0 < NTOK)
                *(float2*)(Sh + r0 * SROW + col) = make_float2(acc[0], acc[1]);
            if (r0 + 8 < NTOK)
                *(float2*)(Sh + (r0 + 8) * SROW + col) = make_float2(acc[2], acc[3]);
        }
        __syncthreads();

        // ---- softmax with bias+mask folded (98 rows) ----
        for (int row = wid; row < 98; row += 8) {
            int hs = row >= NTOK; int n = row - hs * NTOK;
            int h = hp * 2 + hs;
            float* Sr = sm + SPF + hs * SHS + n * SROW;
            int i0 = n * NTOK + ln;
            float v0 = Sr[ln] + __ldg(bias_table + __ldg(rel_index + i0) * 4 + h) + __ldg(maskw + i0);
            float v1 = -1e30f;
            if (ln + 32 < NTOK) {
                int i1 = i0 + 32;
                v1 = Sr[ln + 32] + __ldg(bias_table + __ldg(rel_index + i1) * 4 + h) + __ldg(maskw + i1);
            }
            float mx = fmaxf(v0, v1);
            #pragma unroll
            for (int o = 16; o; o >>= 1) mx = fmaxf(mx, __shfl_xor_sync(0xffffffffu, mx, o));
            float e0 = __expf(v0 - mx);
            float e1 = (ln + 32 < NTOK) ? __expf(v1 - mx) : 0.f;
            float s = e0 + e1;
            #pragma unroll
            for (int o = 16; o; o >>= 1) s += __shfl_xor_sync(0xffffffffu, s, o);
            float inv = 1.f / s;
            Sr[ln] = e0 * inv;
            if (ln + 32 < NTOK) Sr[ln + 32] = e1 * inv;
        }
        __syncthreads();

        // ---- O = S @ V (ffma2), write fp16 hi/lo ----
        if (tid < 208) {
            int nb = tid >> 4;
            int cb = tid & 15;
            int hs = cb >> 3;
            int h  = hp * 2 + hs;
            int chl = (cb & 7) * 4;
            const float* vb = sm + VPF + h * 32 + chl;
            const float* Srow[4];
            #pragma unroll
            for (int i = 0; i < 4; i++)
                Srow[i] = sm + SPF + hs * SHS + imin(nb * 4 + i, 48) * SROW;
            u64 acc[4][2];
            #pragma unroll
            for (int i = 0; i < 4; i++) { acc[i][0] = 0ull; acc[i][1] = 0ull; }
            #pragma unroll 2
            for (int m = 0; m < NTOK; m++) {
                u64 v0 = *(const u64*)(vb + m * 128);
                u64 v1 = *(const u64*)(vb + m * 128 + 2);
                #pragma unroll
                for (int i = 0; i < 4; i++) {
                    u64 sd = dup2(Srow[i][m]);
                    acc[i][0] = ffma2(sd, v0, acc[i][0]);
                    acc[i][1] = ffma2(sd, v1, acc[i][1]);
                }
            }
            #pragma unroll
            for (int i = 0; i < 4; i++) {
                int n = nb * 4 + i;
                if (n < NTOK) {
                    size_t grow = rbase + (size_t)n * 128 + h * 32 + chl;
                    #pragma unroll
                    for (int jj = 0; jj < 2; jj++) {
                        float o0, o1; unpack2(acc[i][jj], o0, o1);
                        __half h0, l0, h1, l1;
                        fsplit(o0, h0, l0); fsplit(o1, h1, l1);
                        *((__half2*)(g_oh + grow + 2 * jj)) = __halves2half2(h0, h1);
                        *((__half2*)(g_ol + grow + 2 * jj)) = __halves2half2(l0, l1);
                    }
                }
            }
        }
        __syncthreads();
    }
}

// ================= launch =================
extern "C" void kernel_launch(void* const* d_in, const int* in_sizes, int n_in,
                              void* d_out, int out_size)
{
    const float* x = nullptr; const float* qkv_w = nullptr; const float* qkv_b = nullptr;
    const float* proj_w = nullptr; const float* proj_b = nullptr;
    const float* bias_table = nullptr; const float* mask = nullptr;
    const int* rel_index = nullptr;

    for (int i = 0; i < n_in; i++) {
        switch (in_sizes[i]) {
            case 25690112: x          = (const float*)d_in[i]; break;
            case 49152:    qkv_w      = (const float*)d_in[i]; break;
            case 384:      qkv_b      = (const float*)d_in[i]; break;
            case 16384:    proj_w     = (const float*)d_in[i]; break;
            case 128:      proj_b     = (const float*)d_in[i]; break;
            case 676:      bias_table = (const float*)d_in[i]; break;
            case 153664:   mask       = (const float*)d_in[i]; break;
            case 2401:     rel_index  = (const int*)  d_in[i]; break;
            default: break;
        }
    }
    float* out = (float*)d_out;

    cudaFuncSetAttribute(gemm_qkv,   cudaFuncAttributeMaxDynamicSharedMemorySize, GEMM_SMEM);
    cudaFuncSetAttribute(gemm_proj,  cudaFuncAttributeMaxDynamicSharedMemorySize, GEMM_SMEM);
    cudaFuncSetAttribute(attn_kernel, cudaFuncAttributeMaxDynamicSharedMemorySize, ATTN_SMEM);

    cvt_w<<<64, 256>>>(qkv_w, proj_w);
    gemm_qkv<<<1568, 256, GEMM_SMEM>>>(x, qkv_b);
    attn_kernel<<<4096, 256, ATTN_SMEM>>>(bias_table, mask, rel_index);
    gemm_proj<<<1568, 256, GEMM_SMEM>>>(proj_b, out);
}

// round 13
// speedup vs baseline: 2.7373x; 1.0338x over previous
#include <cuda_runtime.h>
#include <cuda_fp16.h>
#include <cstdint>

typedef unsigned long long u64;
typedef unsigned int u32;

#define NROW  200704              // 4096*49
#define NFLAT 25690112            // NROW*128
#define NTOK  49

// ---------------- global scratch ----------------
__device__ __half g_qh[NFLAT];    // Q pre-split fp16 hi/lo (scaled, biased)
__device__ __half g_ql[NFLAT];
__device__ __half g_kh[NFLAT];
__device__ __half g_kl[NFLAT];
__device__ float  g_v[NFLAT];
__device__ __half g_oh[NFLAT];
__device__ __half g_ol[NFLAT];
__device__ __half g_wqh[49152];   // qkv_w, n-major [384][128]
__device__ __half g_wql[49152];
__device__ __half g_wph[16384];   // proj_w, n-major [128][128]
__device__ __half g_wpl[16384];
__device__ float  g_bm[64 * 4 * 2401];   // precomputed bias_table[rel_index]+mask

// ---------------- helpers ----------------
__device__ __forceinline__ void fsplit(float f, __half& h, __half& l) {
    h = __float2half_rn(f);
    l = __float2half_rn(f - __half2float(h));
}
__device__ __forceinline__ u64 ffma2(u64 a, u64 b, u64 c) {
    u64 d; asm("fma.rn.f32x2 %0, %1, %2, %3;" : "=l"(d) : "l"(a), "l"(b), "l"(c)); return d;
}
__device__ __forceinline__ u64 dup2(float x) {
    u64 d; u32 u = __float_as_uint(x);
    asm("mov.b64 %0, {%1, %1};" : "=l"(d) : "r"(u)); return d;
}
__device__ __forceinline__ void unpack2(u64 v, float& x, float& y) {
    u32 ux, uy; asm("mov.b64 {%0, %1}, %2;" : "=r"(ux), "=r"(uy) : "l"(v));
    x = __uint_as_float(ux); y = __uint_as_float(uy);
}
__device__ __forceinline__ int imin(int a, int b) { return a < b ? a : b; }

__device__ __forceinline__ void ldsm_x4(u32* r, u32 addr) {
    asm volatile("ldmatrix.sync.aligned.m8n8.x4.shared.b16 {%0,%1,%2,%3}, [%4];"
                 : "=r"(r[0]), "=r"(r[1]), "=r"(r[2]), "=r"(r[3]) : "r"(addr));
}
__device__ __forceinline__ void ldsm_x2(u32* r, u32 addr) {
    asm volatile("ldmatrix.sync.aligned.m8n8.x2.shared.b16 {%0,%1}, [%2];"
                 : "=r"(r[0]), "=r"(r[1]) : "r"(addr));
}
__device__ __forceinline__ void mma16816(float* c, const u32* a, const u32* b) {
    asm volatile(
        "mma.sync.aligned.m16n8k16.row.col.f32.f16.f16.f32 "
        "{%0,%1,%2,%3}, {%4,%5,%6,%7}, {%8,%9}, {%0,%1,%2,%3};"
        : "+f"(c[0]), "+f"(c[1]), "+f"(c[2]), "+f"(c[3])
        : "r"(a[0]), "r"(a[1]), "r"(a[2]), "r"(a[3]), "r"(b[0]), "r"(b[1]));
}
// byte offset in a [rows][128-fp16] tile: 256 B/row, XOR swizzle on 16B units
__device__ __forceinline__ u32 toff(u32 r, u32 unit) {
    return r * 256 + ((unit ^ (r & 7)) * 16);
}

// ================= K0a: weights -> fp16 hi/lo, n-major =================
__global__ void cvt_w(const float* __restrict__ qkv_w, const float* __restrict__ proj_w) {
    int t = blockIdx.x * blockDim.x + threadIdx.x;
    int st = gridDim.x * blockDim.x;
    for (int i = t; i < 49152; i += st) {
        int n = i >> 7, k = i & 127;
        __half h, l; fsplit(__ldg(qkv_w + k * 384 + n), h, l);
        g_wqh[i] = h; g_wql[i] = l;
    }
    for (int i = t; i < 16384; i += st) {
        int n = i >> 7, k = i & 127;
        __half h, l; fsplit(__ldg(proj_w + k * 128 + n), h, l);
        g_wph[i] = h; g_wpl[i] = l;
    }
}

// ================= K0b: bm[w64][h][n][m] = bias_table[rel_index]+mask ======
__global__ void cvt_bias(const float* __restrict__ bias_table,
                         const float* __restrict__ mask,
                         const int* __restrict__ rel_index) {
    int i = blockIdx.x * blockDim.x + threadIdx.x;
    if (i < 64 * 4 * 2401) {
        int m = i % 2401;
        int h = (i / 2401) & 3;
        int w = i / (4 * 2401);
        g_bm[i] = __ldg(bias_table + __ldg(rel_index + m) * 4 + h) + __ldg(mask + w * 2401 + m);
    }
}

// ================= GEMM (A-resident, N-chunk loop inside) =================
#define SA_H 0
#define SA_L 16384
#define SB_H 32768
#define SB_L 40960
#define GEMM_SMEM (49152 * 2)   // 96 KB

template<bool QKV>
__device__ __forceinline__ void gemm_run(const float* __restrict__ xA,
                                         const __half* Ah16, const __half* Al16,
                                         const __half* Bh, const __half* Bl,
                                         const float* __restrict__ bias,
                                         float* dst0, int nchunks)
{
    extern __shared__ __half sh[];
    const int tid = threadIdx.x;
    const int wid = tid >> 5, ln = tid & 31;
    const int m0 = blockIdx.x * 128;

    // ---- load A (128 rows x 128 k) ----
    if (QKV) {
        for (int i = tid; i < 2048; i += 256) {
            int r = i >> 4, u = i & 15;
            const float* src = xA + (size_t)(m0 + r) * 128 + u * 8;
            float4 fa = __ldg((const float4*)src);
            float4 fb = __ldg((const float4*)(src + 4));
            __half h[8], l[8];
            fsplit(fa.x, h[0], l[0]); fsplit(fa.y, h[1], l[1]);
            fsplit(fa.z, h[2], l[2]); fsplit(fa.w, h[3], l[3]);
            fsplit(fb.x, h[4], l[4]); fsplit(fb.y, h[5], l[5]);
            fsplit(fb.z, h[6], l[6]); fsplit(fb.w, h[7], l[7]);
            u32 off = toff(r, u);
            *(uint4*)((char*)sh + SA_H * 2 + off) = *(uint4*)h;
            *(uint4*)((char*)sh + SA_L * 2 + off) = *(uint4*)l;
        }
    } else {
        const uint4* ah4 = (const uint4*)Ah16 + (size_t)m0 * 16;
        const uint4* al4 = (const uint4*)Al16 + (size_t)m0 * 16;
        for (int i = tid; i < 2048; i += 256) {
            int r = i >> 4, u = i & 15;
            u32 off = toff(r, u);
            *(uint4*)((char*)sh + SA_H * 2 + off) = __ldg(ah4 + i);
            *(uint4*)((char*)sh + SA_L * 2 + off) = __ldg(al4 + i);
        }
    }

    u32 sb;
    asm("{ .reg .u64 t; cvta.to.shared.u64 t, %1; cvt.u32.u64 %0, t; }" : "=r"(sb) : "l"(sh));
    const u32 aH = sb + SA_H * 2, aL = sb + SA_L * 2;
    const u32 bH = sb + SB_H * 2, bL = sb + SB_L * 2;
    const int mw = wid & 3, nw = wid >> 2;
    const float scale = 0.17677669529663687f;

    for (int c = 0; c < nchunks; c++) {
        {
            const uint4* bh4 = (const uint4*)Bh + (size_t)c * 1024;
            const uint4* bl4 = (const uint4*)Bl + (size_t)c * 1024;
            for (int i = tid; i < 1024; i += 256) {
                int r = i >> 4, u = i & 15;
                u32 off = toff(r, u);
                *(uint4*)((char*)sh + SB_H * 2 + off) = __ldg(bh4 + i);
                *(uint4*)((char*)sh + SB_L * 2 + off) = __ldg(bl4 + i);
            }
        }
        __syncthreads();

        float acc[2][4][4];
        #pragma unroll
        for (int i = 0; i < 2; i++)
            #pragma unroll
            for (int j = 0; j < 4; j++)
                #pragma unroll
                for (int q = 0; q < 4; q++) acc[i][j][q] = 0.f;

        #pragma unroll
        for (int kc = 0; kc < 8; kc++) {
            u32 ah[2][4], al[2][4];
            #pragma unroll
            for (int mi = 0; mi < 2; mi++) {
                u32 off = toff(mw * 32 + mi * 16 + (ln & 15), kc * 2 + (ln >> 4));
                ldsm_x4(ah[mi], aH + off);
                ldsm_x4(al[mi], aL + off);
            }
            u32 bhf[4][2], blf[4][2];
            #pragma unroll
            for (int p = 0; p < 2; p++) {
                int g = ln >> 3;
                u32 off = toff(nw * 32 + p * 16 + (g >> 1) * 8 + (ln & 7), kc * 2 + (g & 1));
                u32 t4[4], t4l[4];
                ldsm_x4(t4, bH + off);
                ldsm_x4(t4l, bL + off);
                bhf[2 * p][0] = t4[0];  bhf[2 * p][1] = t4[1];
                bhf[2 * p + 1][0] = t4[2]; bhf[2 * p + 1][1] = t4[3];
                blf[2 * p][0] = t4l[0]; blf[2 * p][1] = t4l[1];
                blf[2 * p + 1][0] = t4l[2]; blf[2 * p + 1][1] = t4l[3];
            }
            #pragma unroll
            for (int mi = 0; mi < 2; mi++)
                #pragma unroll
                for (int nj = 0; nj < 4; nj++) {
                    mma16816(acc[mi][nj], ah[mi], bhf[nj]);
                    mma16816(acc[mi][nj], al[mi], bhf[nj]);
                    mma16816(acc[mi][nj], ah[mi], blf[nj]);
                }
        }

        // ---- epilogue ----
        #pragma unroll
        for (int mi = 0; mi < 2; mi++)
            #pragma unroll
            for (int nj = 0; nj < 4; nj++) {
                int cl = nw * 32 + nj * 8 + 2 * (ln & 3);
                int gcol = c * 64 + cl;
                float b0 = __ldg(bias + gcol), b1 = __ldg(bias + gcol + 1);
                int r = m0 + mw * 32 + mi * 16 + (ln >> 2);
                float v00 = acc[mi][nj][0] + b0, v01 = acc[mi][nj][1] + b1;   // row r
                float v10 = acc[mi][nj][2] + b0, v11 = acc[mi][nj][3] + b1;   // row r+8
                if (QKV) {
                    int col = (c & 1) * 64 + cl;
                    if (c < 4) {      // Q or K -> pre-split fp16 hi/lo
                        float mult = (c < 2) ? scale : 1.f;
                        __half* dh = (c < 2) ? g_qh : g_kh;
                        __half* dl = (c < 2) ? g_ql : g_kl;
                        __half h0, l0, h1, l1;
                        fsplit(v00 * mult, h0, l0); fsplit(v01 * mult, h1, l1);
                        *(__half2*)(dh + (size_t)r * 128 + col) = __halves2half2(h0, h1);
                        *(__half2*)(dl + (size_t)r * 128 + col) = __halves2half2(l0, l1);
                        fsplit(v10 * mult, h0, l0); fsplit(v11 * mult, h1, l1);
                        *(__half2*)(dh + (size_t)(r + 8) * 128 + col) = __halves2half2(h0, h1);
                        *(__half2*)(dl + (size_t)(r + 8) * 128 + col) = __halves2half2(l0, l1);
                    } else {          // V -> fp32
                        *(float2*)(g_v + (size_t)r * 128 + col) = make_float2(v00, v01);
                        *(float2*)(g_v + (size_t)(r + 8) * 128 + col) = make_float2(v10, v11);
                    }
                } else {
                    *(float2*)(dst0 + (size_t)r * 128 + gcol) = make_float2(v00, v01);
                    *(float2*)(dst0 + (size_t)(r + 8) * 128 + gcol) = make_float2(v10, v11);
                }
            }
        __syncthreads();
    }
}

__global__ __launch_bounds__(256, 2)
void gemm_qkv(const float* __restrict__ x, const float* __restrict__ qkv_b) {
    gemm_run<true>(x, nullptr, nullptr, g_wqh, g_wql, qkv_b, nullptr, 6);
}
__global__ __launch_bounds__(256, 2)
void gemm_proj(const float* __restrict__ proj_b, float* __restrict__ out) {
    gemm_run<false>(nullptr, g_oh, g_ol, g_wph, g_wpl, proj_b, out, 2);
}

// ================= attention =================
// smem (bytes): fp16 tiles QH@0 QL@16384 KH@32768 KL@49152 (each 64x128 fp16, swizzled)
// floats: S @ 16384 fl (2 heads x 49 x 56), V @ VPF (49 x 128)
#define SPF 16384
#define SROW 56
#define SHS (NTOK * SROW)        // 2744
#define VPF (SPF + 2 * SHS)      // 21872
#define ATTN_SMEM ((VPF + NTOK * 128) * 4)   // 112,576 B

__global__ __launch_bounds__(256, 2)
void attn_kernel(void)
{
    extern __shared__ float sm[];
    char* smc = (char*)sm;
    const int tid = threadIdx.x;
    const int wid = tid >> 5, ln = tid & 31;
    const int win = blockIdx.x;
    const size_t rbase = (size_t)win * NTOK * 128;

    u32 sb;
    asm("{ .reg .u64 t; cvta.to.shared.u64 t, %1; cvt.u32.u64 %0, t; }" : "=r"(sb) : "l"(sm));
    const u32 QHb = sb, QLb = sb + 16384, KHb = sb + 32768, KLb = sb + 49152;

    // ---- load Q/K fp16 hi/lo (pre-split) -> swizzled tiles; V -> fp32 ----
    {
        const uint4* qh4 = (const uint4*)(g_qh + rbase);
        const uint4* ql4 = (const uint4*)(g_ql + rbase);
        const uint4* kh4 = (const uint4*)(g_kh + rbase);
        const uint4* kl4 = (const uint4*)(g_kl + rbase);
        const uint4 z = make_uint4(0, 0, 0, 0);
        for (int i = tid; i < 1024; i += 256) {     // 64 rows x 16 units
            int r = i >> 4, u = i & 15;
            bool v = r < NTOK;
            uint4 qh = v ? __ldg(qh4 + i) : z;
            uint4 ql = v ? __ldg(ql4 + i) : z;
            uint4 kh = v ? __ldg(kh4 + i) : z;
            uint4 kl = v ? __ldg(kl4 + i) : z;
            u32 off = toff(r, u);
            *(uint4*)(smc + off)         = qh;
            *(uint4*)(smc + 16384 + off) = ql;
            *(uint4*)(smc + 32768 + off) = kh;
            *(uint4*)(smc + 49152 + off) = kl;
        }
    }
    for (int i = tid; i < NTOK * 32; i += 256) {
        int r = i >> 5, cq = i & 31;
        *(float4*)(sm + VPF + r * 128 + cq * 4) =
            __ldg((const float4*)(g_v + rbase + (size_t)r * 128) + cq);
    }
    __syncthreads();

    const float* bmw = g_bm + (size_t)(win & 63) * 4 * 2401;

    for (int hp = 0; hp < 2; hp++) {
        // ---- QK^T via HMMA (2 heads x 4 Mt x 7 Nt = 56 warp jobs) ----
        for (int job = wid; job < 56; job += 8) {
            int hs = job / 28; int r2 = job - hs * 28;
            int Mt = r2 / 7, Nt = r2 - Mt * 7;
            int h = hp * 2 + hs;
            float acc[4] = {0.f, 0.f, 0.f, 0.f};
            #pragma unroll
            for (int kc = 0; kc < 2; kc++) {
                u32 ah[4], al[4];
                u32 aoff = toff(Mt * 16 + (ln & 15), h * 4 + kc * 2 + (ln >> 4));
                ldsm_x4(ah, QHb + aoff);
                ldsm_x4(al, QLb + aoff);
                u32 bh[2], bl[2];
                u32 boff = toff(Nt * 8 + (ln & 7), h * 4 + kc * 2 + ((ln >> 3) & 1));
                ldsm_x2(bh, KHb + boff);
                ldsm_x2(bl, KLb + boff);
                mma16816(acc, ah, bh);
                mma16816(acc, al, bh);
                mma16816(acc, ah, bl);
            }
            float* Sh = sm + SPF + hs * SHS;
            int r0 = Mt * 16 + (ln >> 2);
            int col = Nt * 8 + 2 * (ln & 3);
            if (r0 < NTOK)
                *(float2*)(Sh + r0 * SROW + col) = make_float2(acc[0], acc[1]);
            if (r0 + 8 < NTOK)
                *(float2*)(Sh + (r0 + 8) * SROW + col) = make_float2(acc[2], acc[3]);
        }
        __syncthreads();

        // ---- softmax with precomputed bias+mask (98 rows) ----
        for (int row = wid; row < 98; row += 8) {
            int hs = row >= NTOK; int n = row - hs * NTOK;
            int h = hp * 2 + hs;
            const float* bmr = bmw + h * 2401 + n * NTOK;
            float* Sr = sm + SPF + hs * SHS + n * SROW;
            float v0 = Sr[ln] + __ldg(bmr + ln);
            float v1 = -1e30f;
            if (ln + 32 < NTOK)
                v1 = Sr[ln + 32] + __ldg(bmr + ln + 32);
            float mx = fmaxf(v0, v1);
            #pragma unroll
            for (int o = 16; o; o >>= 1) mx = fmaxf(mx, __shfl_xor_sync(0xffffffffu, mx, o));
            float e0 = __expf(v0 - mx);
            float e1 = (ln + 32 < NTOK) ? __expf(v1 - mx) : 0.f;
            float s = e0 + e1;
            #pragma unroll
            for (int o = 16; o; o >>= 1) s += __shfl_xor_sync(0xffffffffu, s, o);
            float inv = 1.f / s;
            Sr[ln] = e0 * inv;
            if (ln + 32 < NTOK) Sr[ln + 32] = e1 * inv;
        }
        __syncthreads();

        // ---- O = S @ V (ffma2), write fp16 hi/lo ----
        if (tid < 208) {
            int nb = tid >> 4;
            int cb = tid & 15;
            int hs = cb >> 3;
            int h  = hp * 2 + hs;
            int chl = (cb & 7) * 4;
            const float* vb = sm + VPF + h * 32 + chl;
            const float* Srow[4];
            #pragma unroll
            for (int i = 0; i < 4; i++)
                Srow[i] = sm + SPF + hs * SHS + imin(nb * 4 + i, 48) * SROW;
            u64 acc[4][2];
            #pragma unroll
            for (int i = 0; i < 4; i++) { acc[i][0] = 0ull; acc[i][1] = 0ull; }
            #pragma unroll 2
            for (int m = 0; m < NTOK; m++) {
                u64 v0 = *(const u64*)(vb + m * 128);
                u64 v1 = *(const u64*)(vb + m * 128 + 2);
                #pragma unroll
                for (int i = 0; i < 4; i++) {
                    u64 sd = dup2(Srow[i][m]);
                    acc[i][0] = ffma2(sd, v0, acc[i][0]);
                    acc[i][1] = ffma2(sd, v1, acc[i][1]);
                }
            }
            #pragma unroll
            for (int i = 0; i < 4; i++) {
                int n = nb * 4 + i;
                if (n < NTOK) {
                    size_t grow = rbase + (size_t)n * 128 + h * 32 + chl;
                    #pragma unroll
                    for (int jj = 0; jj < 2; jj++) {
                        float o0, o1; unpack2(acc[i][jj], o0, o1);
                        __half h0, l0, h1, l1;
                        fsplit(o0, h0, l0); fsplit(o1, h1, l1);
                        *((__half2*)(g_oh + grow + 2 * jj)) = __halves2half2(h0, h1);
                        *((__half2*)(g_ol + grow + 2 * jj)) = __halves2half2(l0, l1);
                    }
                }
            }
        }
        __syncthreads();
    }
}

// ================= launch =================
extern "C" void kernel_launch(void* const* d_in, const int* in_sizes, int n_in,
                              void* d_out, int out_size)
{
    const float* x = nullptr; const float* qkv_w = nullptr; const float* qkv_b = nullptr;
    const float* proj_w = nullptr; const float* proj_b = nullptr;
    const float* bias_table = nullptr; const float* mask = nullptr;
    const int* rel_index = nullptr;

    for (int i = 0; i < n_in; i++) {
        switch (in_sizes[i]) {
            case 25690112: x          = (const float*)d_in[i]; break;
            case 49152:    qkv_w      = (const float*)d_in[i]; break;
            case 384:      qkv_b      = (const float*)d_in[i]; break;
            case 16384:    proj_w     = (const float*)d_in[i]; break;
            case 128:      proj_b     = (const float*)d_in[i]; break;
            case 676:      bias_table = (const float*)d_in[i]; break;
            case 153664:   mask       = (const float*)d_in[i]; break;
            case 2401:     rel_index  = (const int*)  d_in[i]; break;
            default: break;
        }
    }
    float* out = (float*)d_out;

    cudaFuncSetAttribute(gemm_qkv,   cudaFuncAttributeMaxDynamicSharedMemorySize, GEMM_SMEM);
    cudaFuncSetAttribute(gemm_proj,  cudaFuncAttributeMaxDynamicSharedMemorySize, GEMM_SMEM);
    cudaFuncSetAttribute(attn_kernel, cudaFuncAttributeMaxDynamicSharedMemorySize, ATTN_SMEM);

    cvt_w<<<64, 256>>>(qkv_w, proj_w);
    cvt_bias<<<(64 * 4 * 2401 + 255) / 256, 256>>>(bias_table, mask, rel_index);
    gemm_qkv<<<1568, 256, GEMM_SMEM>>>(x, qkv_b);
    attn_kernel<<<4096, 256, ATTN_SMEM>>>();
    gemm_proj<<<1568, 256, GEMM_SMEM>>>(proj_b, out);
}

// round 15
// speedup vs baseline: 4.2999x; 1.5708x over previous
#include <cuda_runtime.h>
#include <cuda_fp16.h>
#include <cstdint>

typedef unsigned long long u64;
typedef unsigned int u32;

#define NROW  200704              // 4096*49
#define NFLAT 25690112            // NROW*128
#define NTOK  49

// ---------------- global scratch ----------------
__device__ __half g_qh[NFLAT];    // Q/K/V pre-split fp16 hi/lo (Q scaled+biased)
__device__ __half g_ql[NFLAT];
__device__ __half g_kh[NFLAT];
__device__ __half g_kl[NFLAT];
__device__ __half g_vh[NFLAT];
__device__ __half g_vl[NFLAT];
__device__ __half g_wqh[49152];   // qkv_w, n-major [384][128]
__device__ __half g_wql[49152];
__device__ __half g_wph[16384];   // proj_w, n-major [128][128]
__device__ __half g_wpl[16384];
__device__ float  g_bm[64 * 4 * 2401 + 8];   // bias[rel_index]+mask, +pad for clamped OOB reads

// ---------------- helpers ----------------
__device__ __forceinline__ void fsplit(float f, __half& h, __half& l) {
    h = __float2half_rn(f);
    l = __float2half_rn(f - __half2float(h));
}
__device__ __forceinline__ int imin(int a, int b) { return a < b ? a : b; }

__device__ __forceinline__ void ldsm_x4(u32* r, u32 addr) {
    asm volatile("ldmatrix.sync.aligned.m8n8.x4.shared.b16 {%0,%1,%2,%3}, [%4];"
                 : "=r"(r[0]), "=r"(r[1]), "=r"(r[2]), "=r"(r[3]) : "r"(addr));
}
__device__ __forceinline__ void ldsm_x2(u32* r, u32 addr) {
    asm volatile("ldmatrix.sync.aligned.m8n8.x2.shared.b16 {%0,%1}, [%2];"
                 : "=r"(r[0]), "=r"(r[1]) : "r"(addr));
}
__device__ __forceinline__ void ldsm_x2t(u32* r, u32 addr) {
    asm volatile("ldmatrix.sync.aligned.m8n8.x2.trans.shared.b16 {%0,%1}, [%2];"
                 : "=r"(r[0]), "=r"(r[1]) : "r"(addr));
}
__device__ __forceinline__ void mma16816(float* c, const u32* a, const u32* b) {
    asm volatile(
        "mma.sync.aligned.m16n8k16.row.col.f32.f16.f16.f32 "
        "{%0,%1,%2,%3}, {%4,%5,%6,%7}, {%8,%9}, {%0,%1,%2,%3};"
        : "+f"(c[0]), "+f"(c[1]), "+f"(c[2]), "+f"(c[3])
        : "r"(a[0]), "r"(a[1]), "r"(a[2]), "r"(a[3]), "r"(b[0]), "r"(b[1]));
}
// byte offset in a [64 rows][128-fp16] tile: 256 B/row, XOR swizzle on 16B units
__device__ __forceinline__ u32 toff(u32 r, u32 unit) {
    return r * 256 + ((unit ^ (r & 7)) * 16);
}
// pack two floats to fp16 hi pair + lo (residual) pair
__device__ __forceinline__ u32 packsplit(float a, float b, u32& lo) {
    __half ha = __float2half_rn(a), hb = __float2half_rn(b);
    __half la = __float2half_rn(a - __half2float(ha));
    __half lb = __float2half_rn(b - __half2float(hb));
    lo = ((u32)__half_as_ushort(lb) << 16) | __half_as_ushort(la);
    return ((u32)__half_as_ushort(hb) << 16) | __half_as_ushort(ha);
}

// ================= K0a: weights -> fp16 hi/lo, n-major =================
__global__ void cvt_w(const float* __restrict__ qkv_w, const float* __restrict__ proj_w) {
    int t = blockIdx.x * blockDim.x + threadIdx.x;
    int st = gridDim.x * blockDim.x;
    for (int i = t; i < 49152; i += st) {
        int n = i >> 7, k = i & 127;
        __half h, l; fsplit(__ldg(qkv_w + k * 384 + n), h, l);
        g_wqh[i] = h; g_wql[i] = l;
    }
    for (int i = t; i < 16384; i += st) {
        int n = i >> 7, k = i & 127;
        __half h, l; fsplit(__ldg(proj_w + k * 128 + n), h, l);
        g_wph[i] = h; g_wpl[i] = l;
    }
}

// ================= K0b: bm[w64][h][n][m] =================
__global__ void cvt_bias(const float* __restrict__ bias_table,
                         const float* __restrict__ mask,
                         const int* __restrict__ rel_index) {
    int i = blockIdx.x * blockDim.x + threadIdx.x;
    if (i < 64 * 4 * 2401) {
        int m = i % 2401;
        int h = (i / 2401) & 3;
        int w = i / (4 * 2401);
        g_bm[i] = __ldg(bias_table + __ldg(rel_index + m) * 4 + h) + __ldg(mask + w * 2401 + m);
    }
}

// ================= K1: qkv GEMM =================
#define SA_H 0
#define SA_L 16384
#define SB_H 32768
#define SB_L 40960
#define GEMM_SMEM (49152 * 2)   // 96 KB

__global__ __launch_bounds__(256, 2)
void gemm_qkv(const float* __restrict__ xA, const float* __restrict__ qkv_b)
{
    extern __shared__ __half sh[];
    const int tid = threadIdx.x;
    const int wid = tid >> 5, ln = tid & 31;
    const int m0 = blockIdx.x * 128;

    for (int i = tid; i < 2048; i += 256) {
        int r = i >> 4, u = i & 15;
        const float* src = xA + (size_t)(m0 + r) * 128 + u * 8;
        float4 fa = __ldg((const float4*)src);
        float4 fb = __ldg((const float4*)(src + 4));
        __half h[8], l[8];
        fsplit(fa.x, h[0], l[0]); fsplit(fa.y, h[1], l[1]);
        fsplit(fa.z, h[2], l[2]); fsplit(fa.w, h[3], l[3]);
        fsplit(fb.x, h[4], l[4]); fsplit(fb.y, h[5], l[5]);
        fsplit(fb.z, h[6], l[6]); fsplit(fb.w, h[7], l[7]);
        u32 off = toff(r, u);
        *(uint4*)((char*)sh + SA_H * 2 + off) = *(uint4*)h;
        *(uint4*)((char*)sh + SA_L * 2 + off) = *(uint4*)l;
    }

    u32 sb;
    asm("{ .reg .u64 t; cvta.to.shared.u64 t, %1; cvt.u32.u64 %0, t; }" : "=r"(sb) : "l"(sh));
    const u32 aH = sb + SA_H * 2, aL = sb + SA_L * 2;
    const u32 bH = sb + SB_H * 2, bL = sb + SB_L * 2;
    const int mw = wid & 3, nw = wid >> 2;
    const float scale = 0.17677669529663687f;

    for (int c = 0; c < 6; c++) {
        {
            const uint4* bh4 = (const uint4*)g_wqh + (size_t)c * 1024;
            const uint4* bl4 = (const uint4*)g_wql + (size_t)c * 1024;
            for (int i = tid; i < 1024; i += 256) {
                int r = i >> 4, u = i & 15;
                u32 off = toff(r, u);
                *(uint4*)((char*)sh + SB_H * 2 + off) = __ldg(bh4 + i);
                *(uint4*)((char*)sh + SB_L * 2 + off) = __ldg(bl4 + i);
            }
        }
        __syncthreads();

        float acc[2][4][4];
        #pragma unroll
        for (int i = 0; i < 2; i++)
            #pragma unroll
            for (int j = 0; j < 4; j++)
                #pragma unroll
                for (int q = 0; q < 4; q++) acc[i][j][q] = 0.f;

        #pragma unroll
        for (int kc = 0; kc < 8; kc++) {
            u32 ah[2][4], al[2][4];
            #pragma unroll
            for (int mi = 0; mi < 2; mi++) {
                u32 off = toff(mw * 32 + mi * 16 + (ln & 15), kc * 2 + (ln >> 4));
                ldsm_x4(ah[mi], aH + off);
                ldsm_x4(al[mi], aL + off);
            }
            u32 bhf[4][2], blf[4][2];
            #pragma unroll
            for (int p = 0; p < 2; p++) {
                int g = ln >> 3;
                u32 off = toff(nw * 32 + p * 16 + (g >> 1) * 8 + (ln & 7), kc * 2 + (g & 1));
                u32 t4[4], t4l[4];
                ldsm_x4(t4, bH + off);
                ldsm_x4(t4l, bL + off);
                bhf[2 * p][0] = t4[0];  bhf[2 * p][1] = t4[1];
                bhf[2 * p + 1][0] = t4[2]; bhf[2 * p + 1][1] = t4[3];
                blf[2 * p][0] = t4l[0]; blf[2 * p][1] = t4l[1];
                blf[2 * p + 1][0] = t4l[2]; blf[2 * p + 1][1] = t4l[3];
            }
            #pragma unroll
            for (int mi = 0; mi < 2; mi++)
                #pragma unroll
                for (int nj = 0; nj < 4; nj++) {
                    mma16816(acc[mi][nj], ah[mi], bhf[nj]);
                    mma16816(acc[mi][nj], al[mi], bhf[nj]);
                    mma16816(acc[mi][nj], ah[mi], blf[nj]);
                }
        }

        // epilogue: all outputs pre-split fp16 hi/lo
        const float mult = (c < 2) ? scale : 1.f;
        __half* dh = (c < 2) ? g_qh : (c < 4) ? g_kh : g_vh;
        __half* dl = (c < 2) ? g_ql : (c < 4) ? g_kl : g_vl;
        #pragma unroll
        for (int mi = 0; mi < 2; mi++)
            #pragma unroll
            for (int nj = 0; nj < 4; nj++) {
                int cl = nw * 32 + nj * 8 + 2 * (ln & 3);
                int gcol = c * 64 + cl;
                float b0 = __ldg(qkv_b + gcol), b1 = __ldg(qkv_b + gcol + 1);
                int col = (c & 1) * 64 + cl;
                int r = m0 + mw * 32 + mi * 16 + (ln >> 2);
                u32 lo, hi;
                hi = packsplit((acc[mi][nj][0] + b0) * mult, (acc[mi][nj][1] + b1) * mult, lo);
                *(u32*)(dh + (size_t)r * 128 + col) = hi;
                *(u32*)(dl + (size_t)r * 128 + col) = lo;
                hi = packsplit((acc[mi][nj][2] + b0) * mult, (acc[mi][nj][3] + b1) * mult, lo);
                *(u32*)(dh + (size_t)(r + 8) * 128 + col) = hi;
                *(u32*)(dl + (size_t)(r + 8) * 128 + col) = lo;
            }
        __syncthreads();
    }
}

// ================= K2: fused attention + proj =================
// smem tiles (16KB each): QH@0 QL@16K KH@32K KL@48K VH@64K VL@80K = 96KB
// after QK/PV: O tiles overlay Q space; proj chunk0 overlays K, chunk1 overlays V
#define QH_O 0
#define QL_O 16384
#define KH_O 32768
#define KL_O 49152
#define VH_O 65536
#define VL_O 81920
#define ATTN_SMEM 98304

__global__ __launch_bounds__(256, 2)
void attn_fused(const float* __restrict__ proj_b, float* __restrict__ out)
{
    extern __shared__ float sm[];
    char* smc = (char*)sm;
    const int tid = threadIdx.x;
    const int wid = tid >> 5, ln = tid & 31;
    const int win = blockIdx.x;
    const size_t rbase = (size_t)win * NTOK * 128;

    u32 sb;
    asm("{ .reg .u64 t; cvta.to.shared.u64 t, %1; cvt.u32.u64 %0, t; }" : "=r"(sb) : "l"(sm));

    // ---- load Q/K/V hi/lo tiles (rows 49..63 zero) ----
    {
        const uint4* s0 = (const uint4*)(g_qh + rbase);
        const uint4* s1 = (const uint4*)(g_ql + rbase);
        const uint4* s2 = (const uint4*)(g_kh + rbase);
        const uint4* s3 = (const uint4*)(g_kl + rbase);
        const uint4* s4 = (const uint4*)(g_vh + rbase);
        const uint4* s5 = (const uint4*)(g_vl + rbase);
        const uint4 z = make_uint4(0, 0, 0, 0);
        for (int i = tid; i < 1024; i += 256) {
            int r = i >> 4, u = i & 15;
            bool v = r < NTOK;
            u32 off = toff(r, u);
            *(uint4*)(smc + QH_O + off) = v ? __ldg(s0 + i) : z;
            *(uint4*)(smc + QL_O + off) = v ? __ldg(s1 + i) : z;
            *(uint4*)(smc + KH_O + off) = v ? __ldg(s2 + i) : z;
            *(uint4*)(smc + KL_O + off) = v ? __ldg(s3 + i) : z;
            *(uint4*)(smc + VH_O + off) = v ? __ldg(s4 + i) : z;
            *(uint4*)(smc + VL_O + off) = v ? __ldg(s5 + i) : z;
        }
    }
    __syncthreads();

    const float* bmw = g_bm + (size_t)(win & 63) * 9604;
    const int h2 = wid >> 2;          // head within pair
    const int Mt = wid & 3;           // 16-row tile
    const int r0 = Mt * 16 + (ln >> 2), r1 = r0 + 8;
    const int c0 = 2 * (ln & 3);

    float accO[2][4][4];
    #pragma unroll
    for (int a = 0; a < 2; a++)
        #pragma unroll
        for (int b = 0; b < 4; b++)
            #pragma unroll
            for (int q = 0; q < 4; q++) accO[a][b][q] = 0.f;

    #pragma unroll
    for (int hp = 0; hp < 2; hp++) {
        const int h = hp * 2 + h2;

        // ---- QK^T: full rows in registers ----
        float acc[7][4];
        #pragma unroll
        for (int nt = 0; nt < 7; nt++)
            #pragma unroll
            for (int q = 0; q < 4; q++) acc[nt][q] = 0.f;

        #pragma unroll
        for (int kc = 0; kc < 2; kc++) {
            u32 qh[4], ql[4];
            u32 aoff = toff(Mt * 16 + (ln & 15), h * 4 + kc * 2 + (ln >> 4));
            ldsm_x4(qh, sb + QH_O + aoff);
            ldsm_x4(ql, sb + QL_O + aoff);
            #pragma unroll
            for (int nt = 0; nt < 7; nt++) {
                u32 boff = toff(nt * 8 + (ln & 7), h * 4 + kc * 2 + ((ln >> 3) & 1));
                u32 bh[2], bl[2];
                ldsm_x2(bh, sb + KH_O + boff);
                ldsm_x2(bl, sb + KL_O + boff);
                mma16816(acc[nt], qh, bh);
                mma16816(acc[nt], ql, bh);
                mma16816(acc[nt], qh, bl);
            }
        }

        // ---- register softmax (bias+mask in; SCALAR loads: row stride 49 is odd,
        //      float2 at bmh+n*49+even_col is only 4B-aligned -> trap) ----
        const float* bmh = bmw + h * 2401;
        const int rr0 = imin(r0, 48) * 49, rr1 = imin(r1, 48) * 49;
        float mx0 = -1e30f, mx1 = -1e30f;
        #pragma unroll
        for (int nt = 0; nt < 7; nt++) {
            int cc = nt * 8 + c0;
            float b00 = __ldg(bmh + rr0 + cc),     b01 = __ldg(bmh + rr0 + cc + 1);
            float b10 = __ldg(bmh + rr1 + cc),     b11 = __ldg(bmh + rr1 + cc + 1);
            acc[nt][0] = (cc     < NTOK) ? acc[nt][0] + b00 : -1e30f;
            acc[nt][1] = (cc + 1 < NTOK) ? acc[nt][1] + b01 : -1e30f;
            acc[nt][2] = (cc     < NTOK) ? acc[nt][2] + b10 : -1e30f;
            acc[nt][3] = (cc + 1 < NTOK) ? acc[nt][3] + b11 : -1e30f;
            mx0 = fmaxf(mx0, fmaxf(acc[nt][0], acc[nt][1]));
            mx1 = fmaxf(mx1, fmaxf(acc[nt][2], acc[nt][3]));
        }
        mx0 = fmaxf(mx0, __shfl_xor_sync(0xffffffffu, mx0, 1));
        mx0 = fmaxf(mx0, __shfl_xor_sync(0xffffffffu, mx0, 2));
        mx1 = fmaxf(mx1, __shfl_xor_sync(0xffffffffu, mx1, 1));
        mx1 = fmaxf(mx1, __shfl_xor_sync(0xffffffffu, mx1, 2));
        float s0 = 0.f, s1 = 0.f;
        #pragma unroll
        for (int nt = 0; nt < 7; nt++) {
            acc[nt][0] = __expf(acc[nt][0] - mx0); s0 += acc[nt][0];
            acc[nt][1] = __expf(acc[nt][1] - mx0); s0 += acc[nt][1];
            acc[nt][2] = __expf(acc[nt][2] - mx1); s1 += acc[nt][2];
            acc[nt][3] = __expf(acc[nt][3] - mx1); s1 += acc[nt][3];
        }
        s0 += __shfl_xor_sync(0xffffffffu, s0, 1);
        s0 += __shfl_xor_sync(0xffffffffu, s0, 2);
        s1 += __shfl_xor_sync(0xffffffffu, s1, 1);
        s1 += __shfl_xor_sync(0xffffffffu, s1, 2);
        float inv0 = 1.f / s0, inv1 = 1.f / s1;

        // ---- pack P fragments in place (A for PV): a = {r0 k, r1 k, r0 k+8, r1 k+8} ----
        u32 ph[4][4], pl[4][4];
        #pragma unroll
        for (int kc = 0; kc < 4; kc++) {
            int n0 = 2 * kc, n1 = 2 * kc + 1;
            ph[kc][0] = packsplit(acc[n0][0] * inv0, acc[n0][1] * inv0, pl[kc][0]);
            ph[kc][1] = packsplit(acc[n0][2] * inv1, acc[n0][3] * inv1, pl[kc][1]);
            if (n1 < 7) {
                ph[kc][2] = packsplit(acc[n1][0] * inv0, acc[n1][1] * inv0, pl[kc][2]);
                ph[kc][3] = packsplit(acc[n1][2] * inv1, acc[n1][3] * inv1, pl[kc][3]);
            } else {
                ph[kc][2] = 0; ph[kc][3] = 0; pl[kc][2] = 0; pl[kc][3] = 0;
            }
        }

        // ---- PV via HMMA with transposed V fragments ----
        #pragma unroll
        for (int kc = 0; kc < 4; kc++) {
            #pragma unroll
            for (int nt = 0; nt < 4; nt++) {
                u32 voff = toff(kc * 16 + (ln & 15), h * 4 + nt);
                u32 vh[2], vl[2];
                ldsm_x2t(vh, sb + VH_O + voff);
                ldsm_x2t(vl, sb + VL_O + voff);
                mma16816(accO[hp][nt], ph[kc], vh);
                mma16816(accO[hp][nt], pl[kc], vh);
                mma16816(accO[hp][nt], ph[kc], vl);
            }
        }
    }
    __syncthreads();   // all QK/PV tile reads done

    // ---- write O hi/lo tiles into dead Q space ----
    #pragma unroll
    for (int hp = 0; hp < 2; hp++) {
        int hh = hp * 2 + h2;
        #pragma unroll
        for (int nt = 0; nt < 4; nt++) {
            int c = hh * 32 + nt * 8 + c0;
            u32 base = toff(r0, c >> 3) + (c & 7) * 2;
            u32 lo, hi;
            hi = packsplit(accO[hp][nt][0], accO[hp][nt][1], lo);
            *(u32*)(smc + QH_O + base) = hi;
            *(u32*)(smc + QL_O + base) = lo;
            u32 base1 = toff(r1, c >> 3) + (c & 7) * 2;
            hi = packsplit(accO[hp][nt][2], accO[hp][nt][3], lo);
            *(u32*)(smc + QH_O + base1) = hi;
            *(u32*)(smc + QL_O + base1) = lo;
        }
    }
    // ---- load proj_w chunks into dead K/V space ----
    {
        const uint4* wh4 = (const uint4*)g_wph;
        const uint4* wl4 = (const uint4*)g_wpl;
        for (int i = tid; i < 2048; i += 256) {
            int chunk = i >> 10, j = i & 1023;
            int r = j >> 4, u = j & 15;
            u32 base = chunk ? VH_O : KH_O;
            u32 off = toff(r, u);
            *(uint4*)(smc + base + off)         = __ldg(wh4 + chunk * 1024 + j);
            *(uint4*)(smc + base + 16384 + off) = __ldg(wl4 + chunk * 1024 + j);
        }
    }
    __syncthreads();

    // ---- fused proj: out = O @ proj_w + proj_b ----
    {
        const int ch = wid >> 2;                 // 64-col chunk
        const u32 BHo = sb + (ch ? VH_O : KH_O);
        float accP[8][4];
        #pragma unroll
        for (int nt = 0; nt < 8; nt++)
            #pragma unroll
            for (int q = 0; q < 4; q++) accP[nt][q] = 0.f;

        #pragma unroll
        for (int kc = 0; kc < 8; kc++) {
            u32 ah[4], al[4];
            u32 aoff = toff(Mt * 16 + (ln & 15), kc * 2 + (ln >> 4));
            ldsm_x4(ah, sb + QH_O + aoff);
            ldsm_x4(al, sb + QL_O + aoff);
            #pragma unroll
            for (int nt = 0; nt < 8; nt++) {
                u32 boff = toff(nt * 8 + (ln & 7), kc * 2 + ((ln >> 3) & 1));
                u32 bh[2], bl[2];
                ldsm_x2(bh, BHo + boff);
                ldsm_x2(bl, BHo + 16384 + boff);
                mma16816(accP[nt], ah, bh);
                mma16816(accP[nt], al, bh);
                mma16816(accP[nt], ah, bl);
            }
        }

        float* og = out + (size_t)win * NTOK * 128;
        #pragma unroll
        for (int nt = 0; nt < 8; nt++) {
            int c = ch * 64 + nt * 8 + c0;
            float pb0 = __ldg(proj_b + c), pb1 = __ldg(proj_b + c + 1);
            if (r0 < NTOK)
                *(float2*)(og + r0 * 128 + c) = make_float2(accP[nt][0] + pb0, accP[nt][1] + pb1);
            if (r1 < NTOK)
                *(float2*)(og + r1 * 128 + c) = make_float2(accP[nt][2] + pb0, accP[nt][3] + pb1);
        }
    }
}

// ================= launch =================
extern "C" void kernel_launch(void* const* d_in, const int* in_sizes, int n_in,
                              void* d_out, int out_size)
{
    const float* x = nullptr; const float* qkv_w = nullptr; const float* qkv_b = nullptr;
    const float* proj_w = nullptr; const float* proj_b = nullptr;
    const float* bias_table = nullptr; const float* mask = nullptr;
    const int* rel_index = nullptr;

    for (int i = 0; i < n_in; i++) {
        switch (in_sizes[i]) {
            case 25690112: x          = (const float*)d_in[i]; break;
            case 49152:    qkv_w      = (const float*)d_in[i]; break;
            case 384:      qkv_b      = (const float*)d_in[i]; break;
            case 16384:    proj_w     = (const float*)d_in[i]; break;
            case 128:      proj_b     = (const float*)d_in[i]; break;
            case 676:      bias_table = (const float*)d_in[i]; break;
            case 153664:   mask       = (const float*)d_in[i]; break;
            case 2401:     rel_index  = (const int*)  d_in[i]; break;
            default: break;
        }
    }
    float* out = (float*)d_out;

    cudaFuncSetAttribute(gemm_qkv,   cudaFuncAttributeMaxDynamicSharedMemorySize, GEMM_SMEM);
    cudaFuncSetAttribute(attn_fused, cudaFuncAttributeMaxDynamicSharedMemorySize, ATTN_SMEM);

    cvt_w<<<64, 256>>>(qkv_w, proj_w);
    cvt_bias<<<(64 * 4 * 2401 + 255) / 256, 256>>>(bias_table, mask, rel_index);
    gemm_qkv<<<1568, 256, GEMM_SMEM>>>(x, qkv_b);
    attn_fused<<<4096, 256, ATTN_SMEM>>>(proj_b, out);
}